// round 1
// baseline (speedup 1.0000x reference)
#include <cuda_runtime.h>
#include <math.h>

#define BATCH   16
#define NNODES  448
#define SEQ     449
#define HDIM    768
#define NHEADS  12
#define DKH     64
#define FFND    3072
#define BDIM    8
#define NLAYER  6
#define OUTD    10
#define INDIM   128
#define EPSV    1e-5f
#define SCALEV  0.125f
#define ROWS    (BATCH*SEQ)   /* 7184 */

// ---------------- scratch (device globals: alloc-free) ----------------
__device__ float g_h  [(size_t)ROWS*HDIM];
__device__ float g_y  [(size_t)ROWS*HDIM];
__device__ float g_q  [(size_t)ROWS*HDIM];
__device__ float g_k  [(size_t)ROWS*HDIM];
__device__ float g_v  [(size_t)ROWS*HDIM];
__device__ float g_o  [(size_t)ROWS*HDIM];
__device__ float g_ffn[(size_t)ROWS*FFND];
__device__ float g_sc [(size_t)BATCH*NHEADS*SEQ*SEQ];

// ---------------- node encoder + graph token ----------------
__global__ void encode_kernel(const float* __restrict__ x, const float* __restrict__ W,
                              const float* __restrict__ b, const float* __restrict__ gt) {
    int r = blockIdx.x;                 // row = b*SEQ + s
    int bb = r / SEQ, s = r % SEQ;
    int tid = threadIdx.x;              // 256
    if (s == NNODES) {
        for (int c = tid; c < HDIM; c += 256) g_h[(size_t)r*HDIM + c] = gt[c];
        return;
    }
    __shared__ float xs[INDIM];
    const float* xr = x + ((size_t)bb*NNODES + s)*INDIM;
    if (tid < INDIM) xs[tid] = xr[tid];
    __syncthreads();
    for (int c = tid; c < HDIM; c += 256) {
        float acc = b[c];
        #pragma unroll 8
        for (int k = 0; k < INDIM; k++) acc += xs[k]*W[k*HDIM + c];
        g_h[(size_t)r*HDIM + c] = acc;
    }
}

// ---------------- layernorm (block per row) ----------------
__global__ void ln_kernel(const float* __restrict__ in, const float* __restrict__ g,
                          const float* __restrict__ bta, float* __restrict__ out) {
    int r = blockIdx.x;
    int tid = threadIdx.x;
    const float* row = in + (size_t)r*HDIM;
    __shared__ float red[256];
    float s = 0.f;
    for (int c = tid; c < HDIM; c += 256) s += row[c];
    red[tid] = s; __syncthreads();
    for (int o = 128; o > 0; o >>= 1) { if (tid < o) red[tid] += red[tid+o]; __syncthreads(); }
    float mean = red[0] * (1.f/HDIM);
    __syncthreads();
    float vs = 0.f;
    for (int c = tid; c < HDIM; c += 256) { float d = row[c]-mean; vs += d*d; }
    red[tid] = vs; __syncthreads();
    for (int o = 128; o > 0; o >>= 1) { if (tid < o) red[tid] += red[tid+o]; __syncthreads(); }
    float rstd = rsqrtf(red[0]*(1.f/HDIM) + EPSV);
    for (int c = tid; c < HDIM; c += 256)
        out[(size_t)r*HDIM + c] = (row[c]-mean)*rstd*g[c] + bta[c];
}

// ---------------- generic SGEMM: C = act(A@W + bias) [+ Res] ----------------
// A [M,K] rm, W [K,N] rm. BM=128, BN=64, BK=16, 256 thr, 8x4 per thread.
template<bool GELU_F, bool RES_F>
__global__ void gemm_kernel(const float* __restrict__ A, const float* __restrict__ Wt,
                            const float* __restrict__ bias, float* __restrict__ C,
                            const float* __restrict__ Res, int M, int N, int K) {
    const int BM=128, BN=64, BK=16, TM=8, TN=4;
    __shared__ float As[BK][BM+1];
    __shared__ float Bs[BK][BN];
    int tid = threadIdx.x;
    int tx = tid % 16, ty = tid / 16;
    int mbase = blockIdx.y*BM;
    int nbase = blockIdx.x*BN;
    float acc[TM][TN];
    #pragma unroll
    for (int i = 0; i < TM; i++)
        #pragma unroll
        for (int j = 0; j < TN; j++) acc[i][j] = 0.f;

    for (int k0 = 0; k0 < K; k0 += BK) {
        #pragma unroll
        for (int i = 0; i < 8; i++) {               // 2048 A elems
            int idx = tid + i*256;
            int ak = idx % BK, am = idx / BK;
            int gm = mbase + am;
            As[ak][am] = (gm < M) ? A[(size_t)gm*K + (k0+ak)] : 0.f;
        }
        #pragma unroll
        for (int i = 0; i < 4; i++) {               // 1024 B elems
            int idx = tid + i*256;
            int bn = idx % BN, bk = idx / BN;
            int gn = nbase + bn;
            Bs[bk][bn] = (gn < N) ? Wt[(size_t)(k0+bk)*N + gn] : 0.f;
        }
        __syncthreads();
        #pragma unroll
        for (int kk = 0; kk < BK; kk++) {
            float a[TM], bv[TN];
            #pragma unroll
            for (int i = 0; i < TM; i++) a[i] = As[kk][ty*TM+i];
            #pragma unroll
            for (int j = 0; j < TN; j++) bv[j] = Bs[kk][tx*TN+j];
            #pragma unroll
            for (int i = 0; i < TM; i++)
                #pragma unroll
                for (int j = 0; j < TN; j++) acc[i][j] += a[i]*bv[j];
        }
        __syncthreads();
    }
    #pragma unroll
    for (int i = 0; i < TM; i++) {
        int r = mbase + ty*TM + i;
        if (r >= M) continue;
        #pragma unroll
        for (int j = 0; j < TN; j++) {
            int c = nbase + tx*TN + j;
            if (c >= N) continue;
            float v = acc[i][j] + bias[c];
            if (GELU_F) v = 0.5f*v*(1.f + erff(v*0.70710678118654752f));
            if (RES_F)  v += Res[(size_t)r*N + c];
            C[(size_t)r*N + c] = v;
        }
    }
}

// ---------------- attention scores: scale*QK^T + fused pairwise bias ----------------
// grid (ceil(SEQ/32), ceil(SEQ/32), B*NHEADS), block (32,32)
__global__ void scores_kernel(const float* __restrict__ ab, const float* __restrict__ gvd,
                              const float* __restrict__ Wb, const float* __restrict__ bb) {
    int z = blockIdx.z;
    int b = z / NHEADS, hh = z % NHEADS;
    int q0 = blockIdx.y*32, k0 = blockIdx.x*32;
    __shared__ float Qs[32][65];
    __shared__ float Ks[32][65];
    __shared__ float wb[BDIM];
    __shared__ float gvds;
    int tx = threadIdx.x, ty = threadIdx.y;
    int tid = ty*32 + tx;
    for (int i = tid; i < 32*64; i += 1024) {
        int r = i / 64, d = i % 64;
        int q = q0 + r;
        Qs[r][d] = (q < SEQ) ? g_q[((size_t)(b*SEQ+q))*HDIM + hh*DKH + d] : 0.f;
        int k = k0 + r;
        Ks[r][d] = (k < SEQ) ? g_k[((size_t)(b*SEQ+k))*HDIM + hh*DKH + d] : 0.f;
    }
    if (tid < BDIM) wb[tid] = Wb[tid*NHEADS + hh];
    if (tid == 0) {
        float s = bb[hh];
        #pragma unroll
        for (int d = 0; d < BDIM; d++) s += gvd[d]*Wb[d*NHEADS + hh];
        gvds = s;
    }
    __syncthreads();
    int q = q0 + ty, k = k0 + tx;
    if (q >= SEQ || k >= SEQ) return;
    float acc = 0.f;
    #pragma unroll
    for (int d = 0; d < 64; d++) acc += Qs[ty][d]*Ks[tx][d];
    acc *= SCALEV;
    float bias;
    if (q < NNODES && k < NNODES) {
        const float* gbv = ab + (((size_t)b*NNODES + q)*NNODES + k)*BDIM;
        float s = bb[hh];
        #pragma unroll
        for (int d = 0; d < BDIM; d++) s += gbv[d]*wb[d];
        bias = s;
    } else {
        bias = gvds;
    }
    g_sc[((size_t)z*SEQ + q)*SEQ + k] = acc + bias;
}

// ---------------- softmax over k (block per (b,h,q) row) ----------------
__global__ void softmax_kernel() {
    size_t row = blockIdx.x;
    float* p = g_sc + row*SEQ;
    int tid = threadIdx.x;
    __shared__ float red[256];
    float m = -1e30f;
    for (int k = tid; k < SEQ; k += 256) m = fmaxf(m, p[k]);
    red[tid] = m; __syncthreads();
    for (int o = 128; o > 0; o >>= 1) { if (tid < o) red[tid] = fmaxf(red[tid], red[tid+o]); __syncthreads(); }
    m = red[0]; __syncthreads();
    float s = 0.f;
    for (int k = tid; k < SEQ; k += 256) { float e = __expf(p[k]-m); p[k] = e; s += e; }
    red[tid] = s; __syncthreads();
    for (int o = 128; o > 0; o >>= 1) { if (tid < o) red[tid] += red[tid+o]; __syncthreads(); }
    float inv = 1.f/red[0];
    for (int k = tid; k < SEQ; k += 256) p[k] *= inv;
}

// ---------------- AV: o = A @ V per (b,h) ----------------
// grid (ceil(SEQ/16), NHEADS, BATCH), block (64,16)
__global__ void av_kernel() {
    int b = blockIdx.z, hh = blockIdx.y;
    int q0 = blockIdx.x*16;
    int tx = threadIdx.x, ty = threadIdx.y;
    int tid = ty*64 + tx;
    __shared__ float As[16][17];
    __shared__ float Vs[16][64];
    float acc = 0.f;
    size_t scbase = ((size_t)(b*NHEADS + hh))*SEQ*SEQ;
    for (int k0 = 0; k0 < SEQ; k0 += 16) {
        if (tid < 256) {
            int r = tid/16, c = tid%16;
            int q = q0 + r, k = k0 + c;
            As[r][c] = (q < SEQ && k < SEQ) ? g_sc[scbase + (size_t)q*SEQ + k] : 0.f;
        }
        {
            int k = k0 + ty;
            Vs[ty][tx] = (k < SEQ) ? g_v[((size_t)(b*SEQ+k))*HDIM + hh*DKH + tx] : 0.f;
        }
        __syncthreads();
        #pragma unroll
        for (int kk = 0; kk < 16; kk++) acc += As[ty][kk]*Vs[kk][tx];
        __syncthreads();
    }
    int q = q0 + ty;
    if (q < SEQ) g_o[((size_t)(b*SEQ+q))*HDIM + hh*DKH + tx] = acc;
}

// ---------------- readout: logits on node 0 + log_softmax ----------------
__global__ void readout_kernel(const float* __restrict__ W, const float* __restrict__ bo,
                               float* __restrict__ out) {
    int b = blockIdx.x;
    int tid = threadIdx.x;
    const float* y = g_y + (size_t)(b*SEQ)*HDIM;   // s = 0 row
    __shared__ float red[256];
    __shared__ float logits[OUTD];
    float acc[OUTD];
    #pragma unroll
    for (int o = 0; o < OUTD; o++) acc[o] = 0.f;
    for (int k = tid; k < HDIM; k += 256) {
        float yv = y[k];
        #pragma unroll
        for (int o = 0; o < OUTD; o++) acc[o] += yv*W[k*OUTD + o];
    }
    for (int o = 0; o < OUTD; o++) {
        red[tid] = acc[o]; __syncthreads();
        for (int s = 128; s > 0; s >>= 1) { if (tid < s) red[tid] += red[tid+s]; __syncthreads(); }
        if (tid == 0) logits[o] = red[0] + bo[o];
        __syncthreads();
    }
    if (tid == 0) {
        float m = -1e30f;
        for (int o = 0; o < OUTD; o++) m = fmaxf(m, logits[o]);
        float s = 0.f;
        for (int o = 0; o < OUTD; o++) s += expf(logits[o]-m);
        float lse = m + logf(s);
        for (int o = 0; o < OUTD; o++) out[b*OUTD + o] = logits[o] - lse;
    }
}

// ---------------- host-side dispatch ----------------
static void gemm(const float* A, const float* W, const float* bias, float* C,
                 const float* Res, int M, int N, int K, bool gelu, bool res) {
    dim3 grid((N + 63)/64, (M + 127)/128);
    if      ( gelu && !res) gemm_kernel<true ,false><<<grid,256>>>(A,W,bias,C,Res,M,N,K);
    else if (!gelu &&  res) gemm_kernel<false,true ><<<grid,256>>>(A,W,bias,C,Res,M,N,K);
    else if ( gelu &&  res) gemm_kernel<true ,true ><<<grid,256>>>(A,W,bias,C,Res,M,N,K);
    else                    gemm_kernel<false,false><<<grid,256>>>(A,W,bias,C,Res,M,N,K);
}

extern "C" void kernel_launch(void* const* d_in, const int* in_sizes, int n_in,
                              void* d_out, int out_size) {
    const float* attn_bias = (const float*)d_in[0];
    const float* x         = (const float*)d_in[1];
    const float* enc_W     = (const float*)d_in[2];
    const float* enc_b     = (const float*)d_in[3];
    const float* gtok      = (const float*)d_in[4];
    const float* gvd       = (const float*)d_in[5];
    const float* ln1_g     = (const float*)d_in[6];
    const float* ln1_b     = (const float*)d_in[7];
    const float* Wq        = (const float*)d_in[8];
    const float* bq        = (const float*)d_in[9];
    const float* Wk        = (const float*)d_in[10];
    const float* bk        = (const float*)d_in[11];
    const float* Wv        = (const float*)d_in[12];
    const float* bv        = (const float*)d_in[13];
    const float* Wbias     = (const float*)d_in[14];
    const float* bbias     = (const float*)d_in[15];
    const float* Wo        = (const float*)d_in[16];
    const float* bo        = (const float*)d_in[17];
    const float* ln2_g     = (const float*)d_in[18];
    const float* ln2_b     = (const float*)d_in[19];
    const float* W1        = (const float*)d_in[20];
    const float* b1        = (const float*)d_in[21];
    const float* W2        = (const float*)d_in[22];
    const float* b2        = (const float*)d_in[23];
    const float* fln_g     = (const float*)d_in[24];
    const float* fln_b     = (const float*)d_in[25];
    const float* out_W     = (const float*)d_in[26];
    const float* out_b     = (const float*)d_in[27];

    float *h_, *y_, *q_, *k_, *v_, *o_, *ffn_;
    cudaGetSymbolAddress((void**)&h_,  g_h);
    cudaGetSymbolAddress((void**)&y_,  g_y);
    cudaGetSymbolAddress((void**)&q_,  g_q);
    cudaGetSymbolAddress((void**)&k_,  g_k);
    cudaGetSymbolAddress((void**)&v_,  g_v);
    cudaGetSymbolAddress((void**)&o_,  g_o);
    cudaGetSymbolAddress((void**)&ffn_, g_ffn);

    encode_kernel<<<ROWS, 256>>>(x, enc_W, enc_b, gtok);

    const dim3 sgrid((SEQ+31)/32, (SEQ+31)/32, BATCH*NHEADS);
    const dim3 sblk(32, 32);
    const dim3 avgrid((SEQ+15)/16, NHEADS, BATCH);
    const dim3 avblk(64, 16);

    for (int i = 0; i < NLAYER; i++) {
        ln_kernel<<<ROWS, 256>>>(h_, ln1_g + i*HDIM, ln1_b + i*HDIM, y_);
        gemm(y_, Wq + (size_t)i*HDIM*HDIM, bq + i*HDIM, q_, nullptr, ROWS, HDIM, HDIM, false, false);
        gemm(y_, Wk + (size_t)i*HDIM*HDIM, bk + i*HDIM, k_, nullptr, ROWS, HDIM, HDIM, false, false);
        gemm(y_, Wv + (size_t)i*HDIM*HDIM, bv + i*HDIM, v_, nullptr, ROWS, HDIM, HDIM, false, false);
        scores_kernel<<<sgrid, sblk>>>(attn_bias, gvd, Wbias + i*BDIM*NHEADS, bbias + i*NHEADS);
        softmax_kernel<<<BATCH*NHEADS*SEQ, 256>>>();
        av_kernel<<<avgrid, avblk>>>();
        gemm(o_, Wo + (size_t)i*HDIM*HDIM, bo + i*HDIM, h_, h_, ROWS, HDIM, HDIM, false, true);
        ln_kernel<<<ROWS, 256>>>(h_, ln2_g + i*HDIM, ln2_b + i*HDIM, y_);
        gemm(y_, W1 + (size_t)i*HDIM*FFND, b1 + i*FFND, ffn_, nullptr, ROWS, FFND, HDIM, true, false);
        gemm(ffn_, W2 + (size_t)i*FFND*HDIM, b2 + i*HDIM, h_, h_, ROWS, HDIM, FFND, false, true);
    }

    ln_kernel<<<ROWS, 256>>>(h_, fln_g, fln_b, y_);
    readout_kernel<<<BATCH, 256>>>(out_W, out_b, (float*)d_out);
}

// round 4
// speedup vs baseline: 1.2443x; 1.2443x over previous
#include <cuda_runtime.h>
#include <cuda_bf16.h>
#include <math.h>
#include <stdint.h>
#include <string.h>

#define BATCH   16
#define NNODES  448
#define SEQ     449
#define SEQP    452            /* padded score-row pitch (16B-aligned) */
#define HDIM    768
#define NHEADS  12
#define DKH     64
#define FFND    3072
#define BDIM    8
#define NLAYER  6
#define OUTD    10
#define INDIM   128
#define EPSV    1e-5f
#define SCALEV  0.125f
#define ROWS    (BATCH*SEQ)   /* 7184 */

// ---------------- scratch (device globals: alloc-free) ----------------
__device__ float g_h  [(size_t)ROWS*HDIM];
__device__ float g_y  [(size_t)ROWS*HDIM];
__device__ float g_q  [(size_t)ROWS*HDIM];
__device__ float g_k  [(size_t)ROWS*HDIM];
__device__ float g_v  [(size_t)ROWS*HDIM];
__device__ float g_o  [(size_t)ROWS*HDIM];
__device__ float g_ffn[(size_t)ROWS*FFND];
__device__ float g_sc [(size_t)BATCH*NHEADS*SEQ*SEQP];

// ---------------- helpers ----------------
__device__ __forceinline__ uint32_t smem_u32(const void* p) {
    uint32_t a;
    asm("{ .reg .u64 t; cvta.to.shared.u64 t, %1; cvt.u32.u64 %0, t; }" : "=r"(a) : "l"(p));
    return a;
}
__device__ __forceinline__ uint32_t packbf(__nv_bfloat16 a, __nv_bfloat16 b) {
    __nv_bfloat162 t; t.x = a; t.y = b;
    uint32_t u; memcpy(&u, &t, 4); return u;
}

#define LDMX4(r0,r1,r2,r3,addr) \
    asm volatile("ldmatrix.sync.aligned.m8n8.x4.shared.b16 {%0,%1,%2,%3}, [%4];" \
        : "=r"(r0),"=r"(r1),"=r"(r2),"=r"(r3) : "r"(addr))

#define MMA16816(c,a,b) \
    asm volatile("mma.sync.aligned.m16n8k16.row.col.f32.bf16.bf16.f32 " \
        "{%0,%1,%2,%3},{%4,%5,%6,%7},{%8,%9},{%0,%1,%2,%3};" \
        : "+f"((c)[0]),"+f"((c)[1]),"+f"((c)[2]),"+f"((c)[3]) \
        : "r"((a)[0]),"r"((a)[1]),"r"((a)[2]),"r"((a)[3]),"r"((b)[0]),"r"((b)[1]))

// ============== generic bf16x3 MMA GEMM ==============
// C[M,N] = epi(A[M,K] @ B) ; A row-major (lda), B global either [K][N] (BTRANS,
// transposed into smem) or [N][K] (direct). smem B is always [n][k].
// EPI: 0 none, 1 bias, 2 bias+gelu, 3 bias+res, 4 scores(scale+pairwise bias)
// BMODE: 0 none, 1 scores batching, 2 AV batching
template<int EPI, bool BTRANS, int BMODE>
__global__ void __launch_bounds__(256, 2)
mma_gemm(const float* __restrict__ A, const float* __restrict__ B,
         const float* __restrict__ bias, float* __restrict__ C,
         const float* __restrict__ Res, int M, int N, int K,
         int lda, int ldb, int ldc,
         const float* __restrict__ ab, const float* __restrict__ Wb,
         const float* __restrict__ bb, const float* __restrict__ gvd) {
    const int tid = threadIdx.x;
    const int wid = tid >> 5, lane = tid & 31;
    const int mbase = blockIdx.y * 128, nbase = blockIdx.x * 128;
    const int z = blockIdx.z;

    size_t aOff = 0, bOff = 0, cOff = 0;
    if (BMODE == 1) {
        int b = z / NHEADS, h = z - b * NHEADS;
        aOff = bOff = (size_t)b * SEQ * HDIM + h * DKH;
        cOff = (size_t)z * SEQ * SEQP;
    } else if (BMODE == 2) {
        int b = z / NHEADS, h = z - b * NHEADS;
        aOff = (size_t)z * SEQ * SEQP;
        bOff = cOff = (size_t)b * SEQ * HDIM + h * DKH;
    }

    __shared__ __align__(16) __nv_bfloat16 sAh[128][40];
    __shared__ __align__(16) __nv_bfloat16 sAl[128][40];
    __shared__ __align__(16) __nv_bfloat16 sBh[128][40];
    __shared__ __align__(16) __nv_bfloat16 sBl[128][40];

    float acc[2][8][4];
    #pragma unroll
    for (int i = 0; i < 2; i++)
        #pragma unroll
        for (int j = 0; j < 8; j++)
            #pragma unroll
            for (int e = 0; e < 4; e++) acc[i][j][e] = 0.f;

    const int wm = (wid & 3) * 32, wn = (wid >> 2) * 64;
    const uint32_t aHb = smem_u32(&sAh[0][0]), aLb = smem_u32(&sAl[0][0]);
    const uint32_t bHb = smem_u32(&sBh[0][0]), bLb = smem_u32(&sBl[0][0]);

    for (int kc = 0; kc < K; kc += 32) {
        // ---- stage A: 128 x 32 fp32 -> hi/lo bf16, layout [m][k] pitch 40 ----
        #pragma unroll
        for (int p = 0; p < 4; p++) {
            int idx = tid + p * 256;
            int r = idx >> 3, k4 = (idx & 7) << 2;
            int gr = mbase + r;
            float4 f = make_float4(0.f, 0.f, 0.f, 0.f);
            if (gr < M) {
                const float* ap = A + aOff + (size_t)gr * lda + kc + k4;
                if (kc + k4 + 3 < K) f = *(const float4*)ap;
                else {
                    float* fp = (float*)&f;
                    #pragma unroll
                    for (int e = 0; e < 4; e++) if (kc + k4 + e < K) fp[e] = ap[e];
                }
            }
            __nv_bfloat16 h0 = __float2bfloat16(f.x), h1 = __float2bfloat16(f.y);
            __nv_bfloat16 h2 = __float2bfloat16(f.z), h3 = __float2bfloat16(f.w);
            __nv_bfloat16 l0 = __float2bfloat16(f.x - __bfloat162float(h0));
            __nv_bfloat16 l1 = __float2bfloat16(f.y - __bfloat162float(h1));
            __nv_bfloat16 l2 = __float2bfloat16(f.z - __bfloat162float(h2));
            __nv_bfloat16 l3 = __float2bfloat16(f.w - __bfloat162float(h3));
            *(uint2*)&sAh[r][k4] = make_uint2(packbf(h0, h1), packbf(h2, h3));
            *(uint2*)&sAl[r][k4] = make_uint2(packbf(l0, l1), packbf(l2, l3));
        }
        // ---- stage B into [n][k] ----
        if (BTRANS) {
            // global B[k][n] (ldb), transpose on store
            #pragma unroll
            for (int p = 0; p < 4; p++) {
                int idx = tid + p * 256;
                int k = idx >> 5, n4 = (idx & 31) << 2;
                float4 f = make_float4(0.f, 0.f, 0.f, 0.f);
                if (kc + k < K) {
                    const float* bp = B + bOff + (size_t)(kc + k) * ldb + nbase + n4;
                    if (nbase + n4 + 3 < N) f = *(const float4*)bp;
                    else {
                        float* fp = (float*)&f;
                        #pragma unroll
                        for (int e = 0; e < 4; e++) if (nbase + n4 + e < N) fp[e] = bp[e];
                    }
                }
                const float* fp = (const float*)&f;
                #pragma unroll
                for (int e = 0; e < 4; e++) {
                    __nv_bfloat16 hb = __float2bfloat16(fp[e]);
                    sBh[n4 + e][k] = hb;
                    sBl[n4 + e][k] = __float2bfloat16(fp[e] - __bfloat162float(hb));
                }
            }
        } else {
            // global B[n][k] (ldb), direct
            #pragma unroll
            for (int p = 0; p < 4; p++) {
                int idx = tid + p * 256;
                int r = idx >> 3, k4 = (idx & 7) << 2;
                int gn = nbase + r;
                float4 f = make_float4(0.f, 0.f, 0.f, 0.f);
                if (gn < N) {
                    const float* bp = B + bOff + (size_t)gn * ldb + kc + k4;
                    if (kc + k4 + 3 < K) f = *(const float4*)bp;
                    else {
                        float* fp = (float*)&f;
                        #pragma unroll
                        for (int e = 0; e < 4; e++) if (kc + k4 + e < K) fp[e] = bp[e];
                    }
                }
                __nv_bfloat16 h0 = __float2bfloat16(f.x), h1 = __float2bfloat16(f.y);
                __nv_bfloat16 h2 = __float2bfloat16(f.z), h3 = __float2bfloat16(f.w);
                __nv_bfloat16 l0 = __float2bfloat16(f.x - __bfloat162float(h0));
                __nv_bfloat16 l1 = __float2bfloat16(f.y - __bfloat162float(h1));
                __nv_bfloat16 l2 = __float2bfloat16(f.z - __bfloat162float(h2));
                __nv_bfloat16 l3 = __float2bfloat16(f.w - __bfloat162float(h3));
                *(uint2*)&sBh[r][k4] = make_uint2(packbf(h0, h1), packbf(h2, h3));
                *(uint2*)&sBl[r][k4] = make_uint2(packbf(l0, l1), packbf(l2, l3));
            }
        }
        __syncthreads();

        // ---- mma over BK=32 (2 k-steps of 16) ----
        #pragma unroll
        for (int ks = 0; ks < 2; ks++) {
            uint32_t bh[8][2], bl[8][2];
            int bn = ((lane >> 4) << 3) + (lane & 7);
            int bkh = (lane >> 3) & 1;
            #pragma unroll
            for (int g = 0; g < 4; g++) {
                uint32_t off = (uint32_t)(wn + g * 16 + bn) * 80u + (uint32_t)(ks * 16 + bkh * 8) * 2u;
                LDMX4(bh[2*g][0], bh[2*g][1], bh[2*g+1][0], bh[2*g+1][1], bHb + off);
                LDMX4(bl[2*g][0], bl[2*g][1], bl[2*g+1][0], bl[2*g+1][1], bLb + off);
            }
            #pragma unroll
            for (int i = 0; i < 2; i++) {
                int ar = wm + i * 16 + (lane & 15);
                uint32_t off = (uint32_t)ar * 80u + (uint32_t)(ks * 16 + (lane >> 4) * 8) * 2u;
                uint32_t ah[4], al[4];
                LDMX4(ah[0], ah[1], ah[2], ah[3], aHb + off);
                LDMX4(al[0], al[1], al[2], al[3], aLb + off);
                #pragma unroll
                for (int j = 0; j < 8; j++) {
                    MMA16816(acc[i][j], ah, bh[j]);
                    MMA16816(acc[i][j], ah, bl[j]);
                    MMA16816(acc[i][j], al, bh[j]);
                }
            }
        }
        __syncthreads();
    }

    // ---- epilogue ----
    float wbh[BDIM]; float gvds = 0.f; int bz = 0;
    if (EPI == 4) {
        bz = z / NHEADS;
        int h = z - bz * NHEADS;
        #pragma unroll
        for (int d = 0; d < BDIM; d++) wbh[d] = Wb[d * NHEADS + h];
        gvds = bb[h];
        #pragma unroll
        for (int d = 0; d < BDIM; d++) gvds += gvd[d] * wbh[d];
    }

    #pragma unroll
    for (int i = 0; i < 2; i++) {
        #pragma unroll
        for (int hf = 0; hf < 2; hf++) {
            int row = mbase + wm + i * 16 + (lane >> 2) + hf * 8;
            if (row >= M) continue;
            #pragma unroll
            for (int j = 0; j < 8; j++) {
                int col = nbase + wn + j * 8 + (lane & 3) * 2;
                float c0 = acc[i][j][hf * 2 + 0];
                float c1 = acc[i][j][hf * 2 + 1];
                if (EPI == 0) {
                    float* cp = C + cOff + (size_t)row * ldc + col;
                    if (col < N)     cp[0] = c0;
                    if (col + 1 < N) cp[1] = c1;
                } else if (EPI <= 3) {
                    float* cp = C + cOff + (size_t)row * ldc + col;
                    #pragma unroll
                    for (int e = 0; e < 2; e++) {
                        int c = col + e;
                        if (c >= N) continue;
                        float t = (e ? c1 : c0) + bias[c];
                        if (EPI == 2) t = 0.5f * t * (1.f + erff(t * 0.70710678118654752f));
                        if (EPI == 3) t += Res[(size_t)row * ldc + c];
                        cp[e] = t;
                    }
                } else {  // scores
                    float* cp = C + cOff + (size_t)row * ldc + col;
                    #pragma unroll
                    for (int e = 0; e < 2; e++) {
                        int c = col + e;
                        if (c >= N) continue;
                        float bv;
                        if (row < NNODES && c < NNODES) {
                            const float* p = ab + (((size_t)bz * NNODES + row) * NNODES + c) * BDIM;
                            float4 x0 = *(const float4*)p;
                            float4 x1 = *(const float4*)(p + 4);
                            float bbv = gvds - (gvd[0]*wbh[0]+gvd[1]*wbh[1]+gvd[2]*wbh[2]+gvd[3]*wbh[3]
                                               +gvd[4]*wbh[4]+gvd[5]*wbh[5]+gvd[6]*wbh[6]+gvd[7]*wbh[7]);
                            bv = x0.x * wbh[0] + x0.y * wbh[1] + x0.z * wbh[2] + x0.w * wbh[3]
                               + x1.x * wbh[4] + x1.y * wbh[5] + x1.z * wbh[6] + x1.w * wbh[7]
                               + bbv;
                        } else {
                            bv = gvds;
                        }
                        cp[e] = (e ? c1 : c0) * SCALEV + bv;
                    }
                }
            }
        }
    }
}

// ---------------- node encoder + graph token ----------------
__global__ void encode_kernel(const float* __restrict__ x, const float* __restrict__ W,
                              const float* __restrict__ b, const float* __restrict__ gt) {
    int r = blockIdx.x;
    int bb = r / SEQ, s = r % SEQ;
    int tid = threadIdx.x;
    if (s == NNODES) {
        for (int c = tid; c < HDIM; c += 256) g_h[(size_t)r*HDIM + c] = gt[c];
        return;
    }
    __shared__ float xs[INDIM];
    const float* xr = x + ((size_t)bb*NNODES + s)*INDIM;
    if (tid < INDIM) xs[tid] = xr[tid];
    __syncthreads();
    for (int c = tid; c < HDIM; c += 256) {
        float acc = b[c];
        #pragma unroll 8
        for (int k = 0; k < INDIM; k++) acc += xs[k]*W[k*HDIM + c];
        g_h[(size_t)r*HDIM + c] = acc;
    }
}

// ---------------- layernorm ----------------
__global__ void ln_kernel(const float* __restrict__ in, const float* __restrict__ g,
                          const float* __restrict__ bta, float* __restrict__ out) {
    int r = blockIdx.x;
    int tid = threadIdx.x;
    const float* row = in + (size_t)r*HDIM;
    __shared__ float red[256];
    float s = 0.f;
    for (int c = tid; c < HDIM; c += 256) s += row[c];
    red[tid] = s; __syncthreads();
    for (int o = 128; o > 0; o >>= 1) { if (tid < o) red[tid] += red[tid+o]; __syncthreads(); }
    float mean = red[0] * (1.f/HDIM);
    __syncthreads();
    float vs = 0.f;
    for (int c = tid; c < HDIM; c += 256) { float d = row[c]-mean; vs += d*d; }
    red[tid] = vs; __syncthreads();
    for (int o = 128; o > 0; o >>= 1) { if (tid < o) red[tid] += red[tid+o]; __syncthreads(); }
    float rstd = rsqrtf(red[0]*(1.f/HDIM) + EPSV);
    for (int c = tid; c < HDIM; c += 256)
        out[(size_t)r*HDIM + c] = (row[c]-mean)*rstd*g[c] + bta[c];
}

// ---------------- softmax (row pitch SEQP) ----------------
__global__ void softmax_kernel() {
    float* p = g_sc + (size_t)blockIdx.x * SEQP;
    int tid = threadIdx.x;
    __shared__ float red[256];
    float m = -1e30f;
    for (int k = tid; k < SEQ; k += 256) m = fmaxf(m, p[k]);
    red[tid] = m; __syncthreads();
    for (int o = 128; o > 0; o >>= 1) { if (tid < o) red[tid] = fmaxf(red[tid], red[tid+o]); __syncthreads(); }
    m = red[0]; __syncthreads();
    float s = 0.f;
    for (int k = tid; k < SEQ; k += 256) { float e = __expf(p[k]-m); p[k] = e; s += e; }
    red[tid] = s; __syncthreads();
    for (int o = 128; o > 0; o >>= 1) { if (tid < o) red[tid] += red[tid+o]; __syncthreads(); }
    float inv = 1.f/red[0];
    for (int k = tid; k < SEQ; k += 256) p[k] *= inv;
}

// ---------------- readout ----------------
__global__ void readout_kernel(const float* __restrict__ W, const float* __restrict__ bo,
                               float* __restrict__ out) {
    int b = blockIdx.x;
    int tid = threadIdx.x;
    const float* y = g_y + (size_t)(b*SEQ)*HDIM;
    __shared__ float red[256];
    __shared__ float logits[OUTD];
    float acc[OUTD];
    #pragma unroll
    for (int o = 0; o < OUTD; o++) acc[o] = 0.f;
    for (int k = tid; k < HDIM; k += 256) {
        float yv = y[k];
        #pragma unroll
        for (int o = 0; o < OUTD; o++) acc[o] += yv*W[k*OUTD + o];
    }
    for (int o = 0; o < OUTD; o++) {
        red[tid] = acc[o]; __syncthreads();
        for (int s = 128; s > 0; s >>= 1) { if (tid < s) red[tid] += red[tid+s]; __syncthreads(); }
        if (tid == 0) logits[o] = red[0] + bo[o];
        __syncthreads();
    }
    if (tid == 0) {
        float m = -1e30f;
        for (int o = 0; o < OUTD; o++) m = fmaxf(m, logits[o]);
        float s = 0.f;
        for (int o = 0; o < OUTD; o++) s += expf(logits[o]-m);
        float lse = m + logf(s);
        for (int o = 0; o < OUTD; o++) out[b*OUTD + o] = logits[o] - lse;
    }
}

// ---------------- host-side dispatch ----------------
static void w_gemm(const float* A, const float* W, const float* bias, float* C,
                   const float* Res, int M, int N, int K, bool gelu, bool res) {
    dim3 grid(N / 128, (M + 127) / 128, 1);
    if (gelu)
        mma_gemm<2, true, 0><<<grid, 256>>>(A, W, bias, C, nullptr, M, N, K, K, N, N,
                                            nullptr, nullptr, nullptr, nullptr);
    else if (res)
        mma_gemm<3, true, 0><<<grid, 256>>>(A, W, bias, C, Res, M, N, K, K, N, N,
                                            nullptr, nullptr, nullptr, nullptr);
    else
        mma_gemm<1, true, 0><<<grid, 256>>>(A, W, bias, C, nullptr, M, N, K, K, N, N,
                                            nullptr, nullptr, nullptr, nullptr);
}

extern "C" void kernel_launch(void* const* d_in, const int* in_sizes, int n_in,
                              void* d_out, int out_size) {
    const float* attn_bias = (const float*)d_in[0];
    const float* x         = (const float*)d_in[1];
    const float* enc_W     = (const float*)d_in[2];
    const float* enc_b     = (const float*)d_in[3];
    const float* gtok      = (const float*)d_in[4];
    const float* gvd       = (const float*)d_in[5];
    const float* ln1_g     = (const float*)d_in[6];
    const float* ln1_b     = (const float*)d_in[7];
    const float* Wq        = (const float*)d_in[8];
    const float* bq        = (const float*)d_in[9];
    const float* Wk        = (const float*)d_in[10];
    const float* bk        = (const float*)d_in[11];
    const float* Wv        = (const float*)d_in[12];
    const float* bv        = (const float*)d_in[13];
    const float* Wbias     = (const float*)d_in[14];
    const float* bbias     = (const float*)d_in[15];
    const float* Wo        = (const float*)d_in[16];
    const float* bo        = (const float*)d_in[17];
    const float* ln2_g     = (const float*)d_in[18];
    const float* ln2_b     = (const float*)d_in[19];
    const float* W1        = (const float*)d_in[20];
    const float* b1        = (const float*)d_in[21];
    const float* W2        = (const float*)d_in[22];
    const float* b2        = (const float*)d_in[23];
    const float* fln_g     = (const float*)d_in[24];
    const float* fln_b     = (const float*)d_in[25];
    const float* out_W     = (const float*)d_in[26];
    const float* out_b     = (const float*)d_in[27];

    float *h_, *y_, *q_, *k_, *v_, *o_, *ffn_, *sc_;
    cudaGetSymbolAddress((void**)&h_,  g_h);
    cudaGetSymbolAddress((void**)&y_,  g_y);
    cudaGetSymbolAddress((void**)&q_,  g_q);
    cudaGetSymbolAddress((void**)&k_,  g_k);
    cudaGetSymbolAddress((void**)&v_,  g_v);
    cudaGetSymbolAddress((void**)&o_,  g_o);
    cudaGetSymbolAddress((void**)&ffn_, g_ffn);
    cudaGetSymbolAddress((void**)&sc_, g_sc);

    encode_kernel<<<ROWS, 256>>>(x, enc_W, enc_b, gtok);

    const dim3 sgrid((SEQ + 127) / 128, (SEQ + 127) / 128, BATCH * NHEADS);  // 4,4,192
    const dim3 avgrid(1, (SEQ + 127) / 128, BATCH * NHEADS);                 // 1,4,192

    for (int i = 0; i < NLAYER; i++) {
        ln_kernel<<<ROWS, 256>>>(h_, ln1_g + i*HDIM, ln1_b + i*HDIM, y_);
        w_gemm(y_, Wq + (size_t)i*HDIM*HDIM, bq + i*HDIM, q_, nullptr, ROWS, HDIM, HDIM, false, false);
        w_gemm(y_, Wk + (size_t)i*HDIM*HDIM, bk + i*HDIM, k_, nullptr, ROWS, HDIM, HDIM, false, false);
        w_gemm(y_, Wv + (size_t)i*HDIM*HDIM, bv + i*HDIM, v_, nullptr, ROWS, HDIM, HDIM, false, false);
        // scores: A=Q (lda=HDIM), B=K as [n][k] (ldb=HDIM), C=g_sc (ldc=SEQP)
        mma_gemm<4, false, 1><<<sgrid, 256>>>(q_, k_, nullptr, sc_, nullptr,
                                              SEQ, SEQ, DKH, HDIM, HDIM, SEQP,
                                              attn_bias, Wbias + i*BDIM*NHEADS, bbias + i*NHEADS, gvd);
        softmax_kernel<<<BATCH*NHEADS*SEQ, 256>>>();
        // AV: A=probs (lda=SEQP), B=V [k][n] trans (ldb=HDIM), C=g_o (ldc=HDIM)
        mma_gemm<0, true, 2><<<avgrid, 256>>>(sc_, v_, nullptr, o_, nullptr,
                                              SEQ, DKH, SEQ, SEQP, HDIM, HDIM,
                                              nullptr, nullptr, nullptr, nullptr);
        w_gemm(o_, Wo + (size_t)i*HDIM*HDIM, bo + i*HDIM, h_, h_, ROWS, HDIM, HDIM, false, true);
        ln_kernel<<<ROWS, 256>>>(h_, ln2_g + i*HDIM, ln2_b + i*HDIM, y_);
        w_gemm(y_, W1 + (size_t)i*HDIM*FFND, b1 + i*FFND, ffn_, nullptr, ROWS, FFND, HDIM, true, false);
        w_gemm(ffn_, W2 + (size_t)i*FFND*HDIM, b2 + i*HDIM, h_, h_, ROWS, HDIM, FFND, false, true);
    }

    ln_kernel<<<ROWS, 256>>>(h_, fln_g, fln_b, y_);
    readout_kernel<<<BATCH, 256>>>(out_W, out_b, (float*)d_out);
}

// round 5
// speedup vs baseline: 3.0329x; 2.4375x over previous
#include <cuda_runtime.h>
#include <cuda_bf16.h>
#include <math.h>
#include <stdint.h>
#include <string.h>

#define BATCH   16
#define NNODES  448
#define SEQ     449
#define SEQP    452            /* fp32 score row pitch */
#define PPITCH  456            /* bf16 probs / vt row pitch (mult of 8) */
#define HDIM    768
#define NHEADS  12
#define DKH     64
#define FFND    3072
#define BDIM    8
#define NLAYER  6
#define OUTD    10
#define INDIM   128
#define EPSV    1e-5f
#define SCALEV  0.125f
#define ROWS    (BATCH*SEQ)   /* 7184 */

#define HH      ((size_t)HDIM*HDIM)
#define HF      ((size_t)HDIM*FFND)
#define LSTR    (4*HH + 2*HF)
#define SMEM_MMA 81920

typedef __nv_bfloat16 bf16;

// ---------------- scratch (device globals: alloc-free) ----------------
__device__ float g_h [(size_t)ROWS*HDIM];
__device__ float g_y [(size_t)ROWS*HDIM];
__device__ float g_sc[(size_t)BATCH*NHEADS*SEQ*SEQP];

__device__ __align__(16) bf16 g_yh[(size_t)ROWS*HDIM];
__device__ __align__(16) bf16 g_yl[(size_t)ROWS*HDIM];
__device__ __align__(16) bf16 g_qh[(size_t)ROWS*HDIM];
__device__ __align__(16) bf16 g_ql[(size_t)ROWS*HDIM];
__device__ __align__(16) bf16 g_kh[(size_t)ROWS*HDIM];
__device__ __align__(16) bf16 g_kl[(size_t)ROWS*HDIM];
__device__ __align__(16) bf16 g_vh[(size_t)ROWS*HDIM];
__device__ __align__(16) bf16 g_vl[(size_t)ROWS*HDIM];
__device__ __align__(16) bf16 g_oh[(size_t)ROWS*HDIM];
__device__ __align__(16) bf16 g_ol[(size_t)ROWS*HDIM];
__device__ __align__(16) bf16 g_fh[(size_t)ROWS*FFND];
__device__ __align__(16) bf16 g_fl[(size_t)ROWS*FFND];
__device__ __align__(16) bf16 g_ph[(size_t)BATCH*NHEADS*SEQ*PPITCH];
__device__ __align__(16) bf16 g_pl[(size_t)BATCH*NHEADS*SEQ*PPITCH];
__device__ __align__(16) bf16 g_vth[(size_t)BATCH*NHEADS*DKH*PPITCH];
__device__ __align__(16) bf16 g_vtl[(size_t)BATCH*NHEADS*DKH*PPITCH];
__device__ __align__(16) bf16 g_wh[(size_t)NLAYER*LSTR];
__device__ __align__(16) bf16 g_wl[(size_t)NLAYER*LSTR];

// ---------------- helpers ----------------
__device__ __forceinline__ uint32_t smem_u32(const void* p) {
    uint32_t a;
    asm("{ .reg .u64 t; cvta.to.shared.u64 t, %1; cvt.u32.u64 %0, t; }" : "=r"(a) : "l"(p));
    return a;
}
__device__ __forceinline__ uint32_t packbf(bf16 a, bf16 b) {
    __nv_bfloat162 t; t.x = a; t.y = b;
    uint32_t u; memcpy(&u, &t, 4); return u;
}
__device__ __forceinline__ void split_pair(float v0, float v1, bf16* H, bf16* L, size_t idx) {
    bf16 h0 = __float2bfloat16(v0), h1 = __float2bfloat16(v1);
    bf16 l0 = __float2bfloat16(v0 - __bfloat162float(h0));
    bf16 l1 = __float2bfloat16(v1 - __bfloat162float(h1));
    *(uint32_t*)(H + idx) = packbf(h0, h1);
    *(uint32_t*)(L + idx) = packbf(l0, l1);
}
__device__ __forceinline__ void cpa(uint32_t dst, const bf16* src, int bytes) {
    asm volatile("cp.async.cg.shared.global [%0], [%1], 16, %2;"
                 :: "r"(dst), "l"(__cvta_generic_to_global(src)), "r"(bytes));
}
#define CP_COMMIT() asm volatile("cp.async.commit_group;" ::: "memory")
#define CP_WAIT0()  asm volatile("cp.async.wait_group 0;" ::: "memory")
#define CP_WAIT1()  asm volatile("cp.async.wait_group 1;" ::: "memory")

#define LDMX4(r0,r1,r2,r3,addr) \
    asm volatile("ldmatrix.sync.aligned.m8n8.x4.shared.b16 {%0,%1,%2,%3}, [%4];" \
        : "=r"(r0),"=r"(r1),"=r"(r2),"=r"(r3) : "r"(addr))

#define MMA16816(c,a,b) \
    asm volatile("mma.sync.aligned.m16n8k16.row.col.f32.bf16.bf16.f32 " \
        "{%0,%1,%2,%3},{%4,%5,%6,%7},{%8,%9},{%0,%1,%2,%3};" \
        : "+f"((c)[0]),"+f"((c)[1]),"+f"((c)[2]),"+f"((c)[3]) \
        : "r"((a)[0]),"r"((a)[1]),"r"((a)[2]),"r"((a)[3]),"r"((b)[0]),"r"((b)[1]))

// ============== bf16x3 MMA GEMM, pre-split operands, cp.async pipelined ==============
// A: hi/lo bf16 [M][K] row-major (lda). B: hi/lo bf16 [N][K] (ldb).
// EPI: 0 split out (AV), 1 bias+split out (QKV), 2 bias+gelu+split (FFN1),
//      3 bias+res fp32 (Wo/FFN2), 4 scores fp32 (scale + pairwise bias)
// BMODE: 0 none, 1 scores, 2 AV
template<int EPI, int BMODE>
__global__ void __launch_bounds__(256, 2)
mma2(const bf16* __restrict__ Ah, const bf16* __restrict__ Al, int lda,
     const bf16* __restrict__ Bh, const bf16* __restrict__ Bl, int ldb,
     const float* __restrict__ bias,
     float* __restrict__ Cf, bf16* __restrict__ Ch, bf16* __restrict__ Cl,
     const float* __restrict__ Res,
     int M, int N, int K, int ldc,
     const float* __restrict__ ab, const float* __restrict__ Wb,
     const float* __restrict__ bb, const float* __restrict__ gvd) {
    extern __shared__ __align__(16) char smem[];
    const int tid = threadIdx.x, wid = tid >> 5, lane = tid & 31;
    const int mbase = blockIdx.y * 128, nbase = blockIdx.x * 128;
    const int z = blockIdx.z;

    size_t aOff = 0, bOff = 0, cOff = 0;
    if (BMODE == 1) {
        int b = z / NHEADS, h = z - b * NHEADS;
        aOff = bOff = (size_t)b * SEQ * HDIM + h * DKH;
        cOff = (size_t)z * SEQ * SEQP;
    } else if (BMODE == 2) {
        int b = z / NHEADS, h = z - b * NHEADS;
        aOff = (size_t)z * SEQ * PPITCH;
        bOff = (size_t)z * DKH * PPITCH;
        cOff = (size_t)b * SEQ * HDIM + h * DKH;
    }

    const uint32_t sbase = smem_u32(smem);
    float acc[2][8][4];
    #pragma unroll
    for (int i = 0; i < 2; i++)
        #pragma unroll
        for (int j = 0; j < 8; j++)
            #pragma unroll
            for (int e = 0; e < 4; e++) acc[i][j][e] = 0.f;

    const int wm = (wid & 3) * 32, wn = (wid >> 2) * 64;
    const int nkc = (K + 31) >> 5;

    auto stage = [&](int buf, int kc) {
        uint32_t sb0 = sbase + buf * 40960;
        #pragma unroll
        for (int m = 0; m < 2; m++) {
            int c = tid + m * 256;
            int row = c >> 2, k8 = c & 3;
            int kpos = kc + k8 * 8;
            int kb = K - kpos;
            int kbytes = kb <= 0 ? 0 : (kb >= 8 ? 16 : kb * 2);
            int kposc = kb <= 0 ? 0 : kpos;
            uint32_t doff = (uint32_t)row * 80u + (uint32_t)k8 * 16u;
            {
                int gr = mbase + row;
                int ok = (gr < M) ? kbytes : 0;
                int grc = (gr < M) ? gr : 0;
                size_t gi = aOff + (size_t)grc * lda + kposc;
                cpa(sb0 + doff, Ah + gi, ok);
                cpa(sb0 + 10240 + doff, Al + gi, ok);
            }
            {
                int gn = nbase + row;
                int ok = (gn < N) ? kbytes : 0;
                int gnc = (gn < N) ? gn : 0;
                size_t gi = bOff + (size_t)gnc * ldb + kposc;
                cpa(sb0 + 20480 + doff, Bh + gi, ok);
                cpa(sb0 + 30720 + doff, Bl + gi, ok);
            }
        }
        CP_COMMIT();
    };

    stage(0, 0);
    for (int ic = 0; ic < nkc; ic++) {
        int buf = ic & 1;
        if (ic + 1 < nkc) { stage(buf ^ 1, (ic + 1) * 32); CP_WAIT1(); }
        else              { CP_WAIT0(); }
        __syncthreads();

        const uint32_t aHb = sbase + buf * 40960, aLb = aHb + 10240;
        const uint32_t bHb = aHb + 20480, bLb = aHb + 30720;
        #pragma unroll
        for (int ks = 0; ks < 2; ks++) {
            uint32_t bh[8][2], bl[8][2];
            int bn = ((lane >> 4) << 3) + (lane & 7);
            int bkh = (lane >> 3) & 1;
            #pragma unroll
            for (int g = 0; g < 4; g++) {
                uint32_t off = (uint32_t)(wn + g * 16 + bn) * 80u + (uint32_t)(ks * 16 + bkh * 8) * 2u;
                LDMX4(bh[2*g][0], bh[2*g][1], bh[2*g+1][0], bh[2*g+1][1], bHb + off);
                LDMX4(bl[2*g][0], bl[2*g][1], bl[2*g+1][0], bl[2*g+1][1], bLb + off);
            }
            #pragma unroll
            for (int i = 0; i < 2; i++) {
                int ar = wm + i * 16 + (lane & 15);
                uint32_t off = (uint32_t)ar * 80u + (uint32_t)(ks * 16 + (lane >> 4) * 8) * 2u;
                uint32_t ah[4], al[4];
                LDMX4(ah[0], ah[1], ah[2], ah[3], aHb + off);
                LDMX4(al[0], al[1], al[2], al[3], aLb + off);
                #pragma unroll
                for (int j = 0; j < 8; j++) {
                    MMA16816(acc[i][j], ah, bh[j]);
                    MMA16816(acc[i][j], ah, bl[j]);
                    MMA16816(acc[i][j], al, bh[j]);
                }
            }
        }
        __syncthreads();
    }

    // ---- epilogue ----
    float wbh[BDIM]; float gvds = 0.f; float bbv = 0.f; int bz = 0;
    if (EPI == 4) {
        bz = z / NHEADS;
        int h = z - bz * NHEADS;
        #pragma unroll
        for (int d = 0; d < BDIM; d++) wbh[d] = Wb[d * NHEADS + h];
        bbv = bb[h];
        gvds = bbv;
        #pragma unroll
        for (int d = 0; d < BDIM; d++) gvds += gvd[d] * wbh[d];
    }

    #pragma unroll
    for (int i = 0; i < 2; i++) {
        #pragma unroll
        for (int hf = 0; hf < 2; hf++) {
            int row = mbase + wm + i * 16 + (lane >> 2) + hf * 8;
            if (row >= M) continue;
            #pragma unroll
            for (int j = 0; j < 8; j++) {
                int col = nbase + wn + j * 8 + (lane & 3) * 2;
                if (col >= N) continue;
                float c0 = acc[i][j][hf * 2 + 0];
                float c1 = acc[i][j][hf * 2 + 1];
                if (EPI == 0) {
                    split_pair(c0, c1, Ch, Cl, cOff + (size_t)row * ldc + col);
                } else if (EPI == 1) {
                    split_pair(c0 + bias[col], c1 + bias[col + 1], Ch, Cl,
                               (size_t)row * ldc + col);
                } else if (EPI == 2) {
                    float t0 = c0 + bias[col], t1 = c1 + bias[col + 1];
                    t0 = 0.5f * t0 * (1.f + erff(t0 * 0.70710678118654752f));
                    t1 = 0.5f * t1 * (1.f + erff(t1 * 0.70710678118654752f));
                    split_pair(t0, t1, Ch, Cl, (size_t)row * ldc + col);
                } else if (EPI == 3) {
                    size_t idx = (size_t)row * ldc + col;
                    Cf[idx]     = c0 + bias[col]     + Res[idx];
                    Cf[idx + 1] = c1 + bias[col + 1] + Res[idx + 1];
                } else {  // scores
                    float* cp = Cf + cOff + (size_t)row * ldc + col;
                    #pragma unroll
                    for (int e = 0; e < 2; e++) {
                        int c = col + e;
                        if (c >= N) continue;
                        float bv;
                        if (row < NNODES && c < NNODES) {
                            const float* p = ab + (((size_t)bz * NNODES + row) * NNODES + c) * BDIM;
                            float4 x0 = *(const float4*)p;
                            float4 x1 = *(const float4*)(p + 4);
                            bv = x0.x*wbh[0] + x0.y*wbh[1] + x0.z*wbh[2] + x0.w*wbh[3]
                               + x1.x*wbh[4] + x1.y*wbh[5] + x1.z*wbh[6] + x1.w*wbh[7] + bbv;
                        } else {
                            bv = gvds;
                        }
                        cp[e] = (e ? c1 : c0) * SCALEV + bv;
                    }
                }
            }
        }
    }
}

// ---------------- weight transpose + split: W[K][N] -> oh/ol[N][K] ----------------
__global__ void wsplit_tr(const float* __restrict__ W, bf16* __restrict__ oh,
                          bf16* __restrict__ ol, int K, int N) {
    __shared__ float t[32][33];
    int k0 = blockIdx.y * 32, n0 = blockIdx.x * 32;
    int tx = threadIdx.x, ty = threadIdx.y;
    #pragma unroll
    for (int j = 0; j < 32; j += 8)
        t[ty + j][tx] = W[(size_t)(k0 + ty + j) * N + n0 + tx];
    __syncthreads();
    #pragma unroll
    for (int j = 0; j < 32; j += 8) {
        float v = t[tx][ty + j];
        size_t o = (size_t)(n0 + ty + j) * K + k0 + tx;
        bf16 h = __float2bfloat16(v);
        oh[o] = h;
        ol[o] = __float2bfloat16(v - __bfloat162float(h));
    }
}

// ---------------- V transpose: vh/vl [b*SEQ+s][h*64+d] -> vth/vtl [z][d][PPITCH] ----------------
__global__ void vtrans_kernel() {
    int z = blockIdx.z, b = z / NHEADS, h = z - b * NHEADS;
    int s0 = blockIdx.x * 32, d0 = blockIdx.y * 32;
    __shared__ bf16 th[32][33], tl[32][33];
    int tx = threadIdx.x, ty = threadIdx.y;
    #pragma unroll
    for (int j = 0; j < 32; j += 8) {
        int s = s0 + ty + j;
        bf16 vh = __float2bfloat16(0.f), vl = vh;
        if (s < SEQ) {
            size_t idx = (size_t)(b * SEQ + s) * HDIM + h * DKH + d0 + tx;
            vh = g_vh[idx]; vl = g_vl[idx];
        }
        th[ty + j][tx] = vh; tl[ty + j][tx] = vl;
    }
    __syncthreads();
    #pragma unroll
    for (int j = 0; j < 32; j += 8) {
        int d = d0 + ty + j, s = s0 + tx;
        if (s < PPITCH) {
            size_t o = ((size_t)z * DKH + d) * PPITCH + s;
            g_vth[o] = th[tx][ty + j];
            g_vtl[o] = tl[tx][ty + j];
        }
    }
}

// ---------------- node encoder + graph token ----------------
__global__ void encode_kernel(const float* __restrict__ x, const float* __restrict__ W,
                              const float* __restrict__ b, const float* __restrict__ gt) {
    int r = blockIdx.x;
    int bb = r / SEQ, s = r % SEQ;
    int tid = threadIdx.x;
    if (s == NNODES) {
        for (int c = tid; c < HDIM; c += 256) g_h[(size_t)r*HDIM + c] = gt[c];
        return;
    }
    __shared__ float xs[INDIM];
    const float* xr = x + ((size_t)bb*NNODES + s)*INDIM;
    if (tid < INDIM) xs[tid] = xr[tid];
    __syncthreads();
    for (int c = tid; c < HDIM; c += 256) {
        float acc = b[c];
        #pragma unroll 8
        for (int k = 0; k < INDIM; k++) acc += xs[k]*W[k*HDIM + c];
        g_h[(size_t)r*HDIM + c] = acc;
    }
}

// ---------------- layernorm -> split bf16 (optionally fp32) ----------------
template<bool F32OUT>
__global__ void ln_kernel(const float* __restrict__ in, const float* __restrict__ g,
                          const float* __restrict__ bta, bf16* __restrict__ oh,
                          bf16* __restrict__ ol, float* __restrict__ of) {
    int r = blockIdx.x;
    int tid = threadIdx.x;
    const float* row = in + (size_t)r*HDIM;
    __shared__ float red[256];
    float s = 0.f;
    for (int c = tid; c < HDIM; c += 256) s += row[c];
    red[tid] = s; __syncthreads();
    for (int o = 128; o > 0; o >>= 1) { if (tid < o) red[tid] += red[tid+o]; __syncthreads(); }
    float mean = red[0] * (1.f/HDIM);
    __syncthreads();
    float vs = 0.f;
    for (int c = tid; c < HDIM; c += 256) { float d = row[c]-mean; vs += d*d; }
    red[tid] = vs; __syncthreads();
    for (int o = 128; o > 0; o >>= 1) { if (tid < o) red[tid] += red[tid+o]; __syncthreads(); }
    float rstd = rsqrtf(red[0]*(1.f/HDIM) + EPSV);
    for (int c = tid*2; c < HDIM; c += 512) {
        float v0 = (row[c]   - mean)*rstd*g[c]   + bta[c];
        float v1 = (row[c+1] - mean)*rstd*g[c+1] + bta[c+1];
        split_pair(v0, v1, oh, ol, (size_t)r*HDIM + c);
        if (F32OUT) { of[(size_t)r*HDIM + c] = v0; of[(size_t)r*HDIM + c + 1] = v1; }
    }
}

// ---------------- softmax: fp32 scores -> split bf16 probs (padded) ----------------
__global__ void softmax_kernel() {
    size_t row = blockIdx.x;
    float* p = g_sc + row * SEQP;
    int tid = threadIdx.x;
    __shared__ float red[256];
    float m = -1e30f;
    for (int k = tid; k < SEQ; k += 256) m = fmaxf(m, p[k]);
    red[tid] = m; __syncthreads();
    for (int o = 128; o > 0; o >>= 1) { if (tid < o) red[tid] = fmaxf(red[tid], red[tid+o]); __syncthreads(); }
    m = red[0]; __syncthreads();
    float s = 0.f;
    for (int k = tid; k < SEQ; k += 256) { float e = __expf(p[k]-m); p[k] = e; s += e; }
    red[tid] = s; __syncthreads();
    for (int o = 128; o > 0; o >>= 1) { if (tid < o) red[tid] += red[tid+o]; __syncthreads(); }
    float inv = 1.f/red[0];
    bf16* ph = g_ph + row * PPITCH;
    bf16* pl = g_pl + row * PPITCH;
    for (int k = tid*2; k < PPITCH; k += 512) {
        float v0 = (k   < SEQ) ? p[k]   * inv : 0.f;
        float v1 = (k+1 < SEQ) ? p[k+1] * inv : 0.f;
        split_pair(v0, v1, ph, pl, k);
    }
}

// ---------------- readout ----------------
__global__ void readout_kernel(const float* __restrict__ W, const float* __restrict__ bo,
                               float* __restrict__ out) {
    int b = blockIdx.x;
    int tid = threadIdx.x;
    const float* y = g_y + (size_t)(b*SEQ)*HDIM;
    __shared__ float red[256];
    __shared__ float logits[OUTD];
    float acc[OUTD];
    #pragma unroll
    for (int o = 0; o < OUTD; o++) acc[o] = 0.f;
    for (int k = tid; k < HDIM; k += 256) {
        float yv = y[k];
        #pragma unroll
        for (int o = 0; o < OUTD; o++) acc[o] += yv*W[k*OUTD + o];
    }
    for (int o = 0; o < OUTD; o++) {
        red[tid] = acc[o]; __syncthreads();
        for (int s = 128; s > 0; s >>= 1) { if (tid < s) red[tid] += red[tid+s]; __syncthreads(); }
        if (tid == 0) logits[o] = red[0] + bo[o];
        __syncthreads();
    }
    if (tid == 0) {
        float m = -1e30f;
        for (int o = 0; o < OUTD; o++) m = fmaxf(m, logits[o]);
        float s = 0.f;
        for (int o = 0; o < OUTD; o++) s += expf(logits[o]-m);
        float lse = m + logf(s);
        for (int o = 0; o < OUTD; o++) out[b*OUTD + o] = logits[o] - lse;
    }
}

extern "C" void kernel_launch(void* const* d_in, const int* in_sizes, int n_in,
                              void* d_out, int out_size) {
    const float* attn_bias = (const float*)d_in[0];
    const float* x         = (const float*)d_in[1];
    const float* enc_W     = (const float*)d_in[2];
    const float* enc_b     = (const float*)d_in[3];
    const float* gtok      = (const float*)d_in[4];
    const float* gvd       = (const float*)d_in[5];
    const float* ln1_g     = (const float*)d_in[6];
    const float* ln1_b     = (const float*)d_in[7];
    const float* Wq        = (const float*)d_in[8];
    const float* bq        = (const float*)d_in[9];
    const float* Wk        = (const float*)d_in[10];
    const float* bk        = (const float*)d_in[11];
    const float* Wv        = (const float*)d_in[12];
    const float* bv        = (const float*)d_in[13];
    const float* Wbias     = (const float*)d_in[14];
    const float* bbias     = (const float*)d_in[15];
    const float* Wo        = (const float*)d_in[16];
    const float* bo        = (const float*)d_in[17];
    const float* ln2_g     = (const float*)d_in[18];
    const float* ln2_b     = (const float*)d_in[19];
    const float* W1        = (const float*)d_in[20];
    const float* b1        = (const float*)d_in[21];
    const float* W2        = (const float*)d_in[22];
    const float* b2        = (const float*)d_in[23];
    const float* fln_g     = (const float*)d_in[24];
    const float* fln_b     = (const float*)d_in[25];
    const float* out_W     = (const float*)d_in[26];
    const float* out_b     = (const float*)d_in[27];

    float *h_, *y_, *sc_;
    bf16 *yh_, *yl_, *qh_, *ql_, *kh_, *kl_, *vh_, *vl_, *oh_, *ol_, *fh_, *fl_;
    bf16 *ph_, *pl_, *vth_, *vtl_, *wh_, *wl_;
    cudaGetSymbolAddress((void**)&h_,  g_h);
    cudaGetSymbolAddress((void**)&y_,  g_y);
    cudaGetSymbolAddress((void**)&sc_, g_sc);
    cudaGetSymbolAddress((void**)&yh_, g_yh);  cudaGetSymbolAddress((void**)&yl_, g_yl);
    cudaGetSymbolAddress((void**)&qh_, g_qh);  cudaGetSymbolAddress((void**)&ql_, g_ql);
    cudaGetSymbolAddress((void**)&kh_, g_kh);  cudaGetSymbolAddress((void**)&kl_, g_kl);
    cudaGetSymbolAddress((void**)&vh_, g_vh);  cudaGetSymbolAddress((void**)&vl_, g_vl);
    cudaGetSymbolAddress((void**)&oh_, g_oh);  cudaGetSymbolAddress((void**)&ol_, g_ol);
    cudaGetSymbolAddress((void**)&fh_, g_fh);  cudaGetSymbolAddress((void**)&fl_, g_fl);
    cudaGetSymbolAddress((void**)&ph_, g_ph);  cudaGetSymbolAddress((void**)&pl_, g_pl);
    cudaGetSymbolAddress((void**)&vth_, g_vth); cudaGetSymbolAddress((void**)&vtl_, g_vtl);
    cudaGetSymbolAddress((void**)&wh_, g_wh);  cudaGetSymbolAddress((void**)&wl_, g_wl);

    cudaFuncSetAttribute(mma2<0,2>, cudaFuncAttributeMaxDynamicSharedMemorySize, SMEM_MMA);
    cudaFuncSetAttribute(mma2<1,0>, cudaFuncAttributeMaxDynamicSharedMemorySize, SMEM_MMA);
    cudaFuncSetAttribute(mma2<2,0>, cudaFuncAttributeMaxDynamicSharedMemorySize, SMEM_MMA);
    cudaFuncSetAttribute(mma2<3,0>, cudaFuncAttributeMaxDynamicSharedMemorySize, SMEM_MMA);
    cudaFuncSetAttribute(mma2<4,1>, cudaFuncAttributeMaxDynamicSharedMemorySize, SMEM_MMA);

    // ---- weight pre-split (transpose to [N][K]) ----
    const dim3 wb32(32, 8);
    for (int i = 0; i < NLAYER; i++) {
        size_t off = (size_t)i * LSTR;
        wsplit_tr<<<dim3(HDIM/32, HDIM/32), wb32>>>(Wq + i*HH, wh_ + off,        wl_ + off,        HDIM, HDIM);
        wsplit_tr<<<dim3(HDIM/32, HDIM/32), wb32>>>(Wk + i*HH, wh_ + off + HH,   wl_ + off + HH,   HDIM, HDIM);
        wsplit_tr<<<dim3(HDIM/32, HDIM/32), wb32>>>(Wv + i*HH, wh_ + off + 2*HH, wl_ + off + 2*HH, HDIM, HDIM);
        wsplit_tr<<<dim3(HDIM/32, HDIM/32), wb32>>>(Wo + i*HH, wh_ + off + 3*HH, wl_ + off + 3*HH, HDIM, HDIM);
        wsplit_tr<<<dim3(FFND/32, HDIM/32), wb32>>>(W1 + i*HF, wh_ + off + 4*HH, wl_ + off + 4*HH, HDIM, FFND);
        wsplit_tr<<<dim3(HDIM/32, FFND/32), wb32>>>(W2 + i*HF, wh_ + off + 4*HH + HF, wl_ + off + 4*HH + HF, FFND, HDIM);
    }

    encode_kernel<<<ROWS, 256>>>(x, enc_W, enc_b, gtok);

    const dim3 ggrid(HDIM/128, (ROWS + 127)/128);          // 6,57
    const dim3 fgrid(FFND/128, (ROWS + 127)/128);          // 24,57
    const dim3 sgrid((SEQ+127)/128, (SEQ+127)/128, BATCH*NHEADS);  // 4,4,192
    const dim3 avgrid(1, (SEQ+127)/128, BATCH*NHEADS);
    const dim3 vtgrid((SEQ+31)/32, DKH/32, BATCH*NHEADS);  // 15,2,192

    for (int i = 0; i < NLAYER; i++) {
        size_t off = (size_t)i * LSTR;
        ln_kernel<false><<<ROWS, 256>>>(h_, ln1_g + i*HDIM, ln1_b + i*HDIM, yh_, yl_, nullptr);
        mma2<1,0><<<ggrid, 256, SMEM_MMA>>>(yh_, yl_, HDIM, wh_ + off, wl_ + off, HDIM,
            bq + i*HDIM, nullptr, qh_, ql_, nullptr, ROWS, HDIM, HDIM, HDIM,
            nullptr, nullptr, nullptr, nullptr);
        mma2<1,0><<<ggrid, 256, SMEM_MMA>>>(yh_, yl_, HDIM, wh_ + off + HH, wl_ + off + HH, HDIM,
            bk + i*HDIM, nullptr, kh_, kl_, nullptr, ROWS, HDIM, HDIM, HDIM,
            nullptr, nullptr, nullptr, nullptr);
        mma2<1,0><<<ggrid, 256, SMEM_MMA>>>(yh_, yl_, HDIM, wh_ + off + 2*HH, wl_ + off + 2*HH, HDIM,
            bv + i*HDIM, nullptr, vh_, vl_, nullptr, ROWS, HDIM, HDIM, HDIM,
            nullptr, nullptr, nullptr, nullptr);
        vtrans_kernel<<<vtgrid, wb32>>>();
        mma2<4,1><<<sgrid, 256, SMEM_MMA>>>(qh_, ql_, HDIM, kh_, kl_, HDIM,
            nullptr, sc_, nullptr, nullptr, nullptr, SEQ, SEQ, DKH, SEQP,
            attn_bias, Wbias + i*BDIM*NHEADS, bbias + i*NHEADS, gvd);
        softmax_kernel<<<BATCH*NHEADS*SEQ, 256>>>();
        mma2<0,2><<<avgrid, 256, SMEM_MMA>>>(ph_, pl_, PPITCH, vth_, vtl_, PPITCH,
            nullptr, nullptr, oh_, ol_, nullptr, SEQ, DKH, SEQ, HDIM,
            nullptr, nullptr, nullptr, nullptr);
        mma2<3,0><<<ggrid, 256, SMEM_MMA>>>(oh_, ol_, HDIM, wh_ + off + 3*HH, wl_ + off + 3*HH, HDIM,
            bo + i*HDIM, h_, nullptr, nullptr, h_, ROWS, HDIM, HDIM, HDIM,
            nullptr, nullptr, nullptr, nullptr);
        ln_kernel<false><<<ROWS, 256>>>(h_, ln2_g + i*HDIM, ln2_b + i*HDIM, yh_, yl_, nullptr);
        mma2<2,0><<<fgrid, 256, SMEM_MMA>>>(yh_, yl_, HDIM, wh_ + off + 4*HH, wl_ + off + 4*HH, HDIM,
            b1 + i*FFND, nullptr, fh_, fl_, nullptr, ROWS, FFND, HDIM, FFND,
            nullptr, nullptr, nullptr, nullptr);
        mma2<3,0><<<ggrid, 256, SMEM_MMA>>>(fh_, fl_, FFND, wh_ + off + 4*HH + HF, wl_ + off + 4*HH + HF, FFND,
            b2 + i*HDIM, h_, nullptr, nullptr, h_, ROWS, HDIM, FFND, HDIM,
            nullptr, nullptr, nullptr, nullptr);
    }

    ln_kernel<true><<<ROWS, 256>>>(h_, fln_g, fln_b, yh_, yl_, y_);
    readout_kernel<<<BATCH, 256>>>(out_W, out_b, (float*)d_out);
}

// round 6
// speedup vs baseline: 3.4285x; 1.1304x over previous
#include <cuda_runtime.h>
#include <cuda_bf16.h>
#include <math.h>
#include <stdint.h>
#include <string.h>

#define BATCH   16
#define NNODES  448
#define SEQ     449
#define SEQP    452            /* fp32 score row pitch */
#define PPITCH  456            /* bf16 probs / vt row pitch (mult of 8) */
#define PBP     456            /* bias-projection row pitch */
#define HDIM    768
#define NHEADS  12
#define DKH     64
#define FFND    3072
#define BDIM    8
#define NLAYER  6
#define OUTD    10
#define INDIM   128
#define EPSV    1e-5f
#define SCALEV  0.125f
#define ROWS    (BATCH*SEQ)   /* 7184 */

#define HH      ((size_t)HDIM*HDIM)
#define HF      ((size_t)HDIM*FFND)
#define LSTR    (4*HH + 2*HF)
#define SMEM_MMA 81920

typedef __nv_bfloat16 bf16;

// ---------------- scratch (device globals: alloc-free) ----------------
__device__ float g_h [(size_t)ROWS*HDIM];
__device__ float g_y [(size_t)ROWS*HDIM];
__device__ float g_sc[(size_t)BATCH*NHEADS*SEQ*SEQP];

__device__ __align__(16) bf16 g_yh[(size_t)ROWS*HDIM];
__device__ __align__(16) bf16 g_yl[(size_t)ROWS*HDIM];
__device__ __align__(16) bf16 g_qh[(size_t)ROWS*HDIM];
__device__ __align__(16) bf16 g_ql[(size_t)ROWS*HDIM];
__device__ __align__(16) bf16 g_kh[(size_t)ROWS*HDIM];
__device__ __align__(16) bf16 g_kl[(size_t)ROWS*HDIM];
__device__ __align__(16) bf16 g_vh[(size_t)ROWS*HDIM];
__device__ __align__(16) bf16 g_vl[(size_t)ROWS*HDIM];
__device__ __align__(16) bf16 g_oh[(size_t)ROWS*HDIM];
__device__ __align__(16) bf16 g_ol[(size_t)ROWS*HDIM];
__device__ __align__(16) bf16 g_fh[(size_t)ROWS*FFND];
__device__ __align__(16) bf16 g_fl[(size_t)ROWS*FFND];
__device__ __align__(16) bf16 g_ph[(size_t)BATCH*NHEADS*SEQ*PPITCH];
__device__ __align__(16) bf16 g_pl[(size_t)BATCH*NHEADS*SEQ*PPITCH];
__device__ __align__(16) bf16 g_vth[(size_t)BATCH*NHEADS*DKH*PPITCH];
__device__ __align__(16) bf16 g_vtl[(size_t)BATCH*NHEADS*DKH*PPITCH];
__device__ __align__(16) bf16 g_wh[(size_t)NLAYER*LSTR];
__device__ __align__(16) bf16 g_wl[(size_t)NLAYER*LSTR];
__device__ __align__(16) bf16 g_pb[(size_t)BATCH*NHEADS*SEQ*PBP];

// ---------------- helpers ----------------
__device__ __forceinline__ uint32_t smem_u32(const void* p) {
    uint32_t a;
    asm("{ .reg .u64 t; cvta.to.shared.u64 t, %1; cvt.u32.u64 %0, t; }" : "=r"(a) : "l"(p));
    return a;
}
__device__ __forceinline__ uint32_t packbf(bf16 a, bf16 b) {
    __nv_bfloat162 t; t.x = a; t.y = b;
    uint32_t u; memcpy(&u, &t, 4); return u;
}
__device__ __forceinline__ void split_pair(float v0, float v1, bf16* H, bf16* L, size_t idx) {
    bf16 h0 = __float2bfloat16(v0), h1 = __float2bfloat16(v1);
    bf16 l0 = __float2bfloat16(v0 - __bfloat162float(h0));
    bf16 l1 = __float2bfloat16(v1 - __bfloat162float(h1));
    *(uint32_t*)(H + idx) = packbf(h0, h1);
    *(uint32_t*)(L + idx) = packbf(l0, l1);
}
__device__ __forceinline__ void cpa(uint32_t dst, const bf16* src, int bytes) {
    asm volatile("cp.async.cg.shared.global [%0], [%1], 16, %2;"
                 :: "r"(dst), "l"(__cvta_generic_to_global(src)), "r"(bytes));
}
#define CP_COMMIT() asm volatile("cp.async.commit_group;" ::: "memory")
#define CP_WAIT0()  asm volatile("cp.async.wait_group 0;" ::: "memory")
#define CP_WAIT1()  asm volatile("cp.async.wait_group 1;" ::: "memory")

#define LDMX4(r0,r1,r2,r3,addr) \
    asm volatile("ldmatrix.sync.aligned.m8n8.x4.shared.b16 {%0,%1,%2,%3}, [%4];" \
        : "=r"(r0),"=r"(r1),"=r"(r2),"=r"(r3) : "r"(addr))

#define MMA16816(c,a,b) \
    asm volatile("mma.sync.aligned.m16n8k16.row.col.f32.bf16.bf16.f32 " \
        "{%0,%1,%2,%3},{%4,%5,%6,%7},{%8,%9},{%0,%1,%2,%3};" \
        : "+f"((c)[0]),"+f"((c)[1]),"+f"((c)[2]),"+f"((c)[3]) \
        : "r"((a)[0]),"r"((a)[1]),"r"((a)[2]),"r"((a)[3]),"r"((b)[0]),"r"((b)[1]))

__device__ __forceinline__ float wred_sum(float v) {
    #pragma unroll
    for (int o = 16; o > 0; o >>= 1) v += __shfl_xor_sync(0xffffffffu, v, o);
    return v;
}
__device__ __forceinline__ float wred_max(float v) {
    #pragma unroll
    for (int o = 16; o > 0; o >>= 1) v = fmaxf(v, __shfl_xor_sync(0xffffffffu, v, o));
    return v;
}

// ============== bf16x3 MMA GEMM, pre-split operands, cp.async pipelined ==============
// EPI: 0 split out (AV), 1 bias+split out (QKV), 2 bias+gelu+split (FFN1),
//      3 bias+res fp32 (Wo/FFN2), 4 scores fp32 (scale + precomputed bf16 bias)
// BMODE: 0 none, 1 scores, 2 AV
template<int EPI, int BMODE>
__global__ void __launch_bounds__(256, 2)
mma2(const bf16* __restrict__ Ah, const bf16* __restrict__ Al, int lda,
     const bf16* __restrict__ Bh, const bf16* __restrict__ Bl, int ldb,
     const float* __restrict__ bias,
     float* __restrict__ Cf, bf16* __restrict__ Ch, bf16* __restrict__ Cl,
     const float* __restrict__ Res,
     int M, int N, int K, int ldc,
     const bf16* __restrict__ pb) {
    extern __shared__ __align__(16) char smem[];
    const int tid = threadIdx.x, wid = tid >> 5, lane = tid & 31;
    const int mbase = blockIdx.y * 128, nbase = blockIdx.x * 128;
    const int z = blockIdx.z;

    size_t aOff = 0, bOff = 0, cOff = 0;
    if (BMODE == 1) {
        int b = z / NHEADS, h = z - b * NHEADS;
        aOff = bOff = (size_t)b * SEQ * HDIM + h * DKH;
        cOff = (size_t)z * SEQ * SEQP;
    } else if (BMODE == 2) {
        int b = z / NHEADS, h = z - b * NHEADS;
        aOff = (size_t)z * SEQ * PPITCH;
        bOff = (size_t)z * DKH * PPITCH;
        cOff = (size_t)b * SEQ * HDIM + h * DKH;
    }

    const uint32_t sbase = smem_u32(smem);
    float acc[2][8][4];
    #pragma unroll
    for (int i = 0; i < 2; i++)
        #pragma unroll
        for (int j = 0; j < 8; j++)
            #pragma unroll
            for (int e = 0; e < 4; e++) acc[i][j][e] = 0.f;

    const int wm = (wid & 3) * 32, wn = (wid >> 2) * 64;
    const int nkc = (K + 31) >> 5;

    auto stage = [&](int buf, int kc) {
        uint32_t sb0 = sbase + buf * 40960;
        #pragma unroll
        for (int m = 0; m < 2; m++) {
            int c = tid + m * 256;
            int row = c >> 2, k8 = c & 3;
            int kpos = kc + k8 * 8;
            int kb = K - kpos;
            int kbytes = kb <= 0 ? 0 : (kb >= 8 ? 16 : kb * 2);
            int kposc = kb <= 0 ? 0 : kpos;
            uint32_t doff = (uint32_t)row * 80u + (uint32_t)k8 * 16u;
            {
                int gr = mbase + row;
                int ok = (gr < M) ? kbytes : 0;
                int grc = (gr < M) ? gr : 0;
                size_t gi = aOff + (size_t)grc * lda + kposc;
                cpa(sb0 + doff, Ah + gi, ok);
                cpa(sb0 + 10240 + doff, Al + gi, ok);
            }
            {
                int gn = nbase + row;
                int ok = (gn < N) ? kbytes : 0;
                int gnc = (gn < N) ? gn : 0;
                size_t gi = bOff + (size_t)gnc * ldb + kposc;
                cpa(sb0 + 20480 + doff, Bh + gi, ok);
                cpa(sb0 + 30720 + doff, Bl + gi, ok);
            }
        }
        CP_COMMIT();
    };

    stage(0, 0);
    for (int ic = 0; ic < nkc; ic++) {
        int buf = ic & 1;
        if (ic + 1 < nkc) { stage(buf ^ 1, (ic + 1) * 32); CP_WAIT1(); }
        else              { CP_WAIT0(); }
        __syncthreads();

        const uint32_t aHb = sbase + buf * 40960, aLb = aHb + 10240;
        const uint32_t bHb = aHb + 20480, bLb = aHb + 30720;
        #pragma unroll
        for (int ks = 0; ks < 2; ks++) {
            uint32_t bh[8][2], bl[8][2];
            int bn = ((lane >> 4) << 3) + (lane & 7);
            int bkh = (lane >> 3) & 1;
            #pragma unroll
            for (int g = 0; g < 4; g++) {
                uint32_t off = (uint32_t)(wn + g * 16 + bn) * 80u + (uint32_t)(ks * 16 + bkh * 8) * 2u;
                LDMX4(bh[2*g][0], bh[2*g][1], bh[2*g+1][0], bh[2*g+1][1], bHb + off);
                LDMX4(bl[2*g][0], bl[2*g][1], bl[2*g+1][0], bl[2*g+1][1], bLb + off);
            }
            #pragma unroll
            for (int i = 0; i < 2; i++) {
                int ar = wm + i * 16 + (lane & 15);
                uint32_t off = (uint32_t)ar * 80u + (uint32_t)(ks * 16 + (lane >> 4) * 8) * 2u;
                uint32_t ah[4], al[4];
                LDMX4(ah[0], ah[1], ah[2], ah[3], aHb + off);
                LDMX4(al[0], al[1], al[2], al[3], aLb + off);
                #pragma unroll
                for (int j = 0; j < 8; j++) {
                    MMA16816(acc[i][j], ah, bh[j]);
                    MMA16816(acc[i][j], ah, bl[j]);
                    MMA16816(acc[i][j], al, bh[j]);
                }
            }
        }
        __syncthreads();
    }

    // ---- epilogue ----
    #pragma unroll
    for (int i = 0; i < 2; i++) {
        #pragma unroll
        for (int hf = 0; hf < 2; hf++) {
            int row = mbase + wm + i * 16 + (lane >> 2) + hf * 8;
            if (row >= M) continue;
            #pragma unroll
            for (int j = 0; j < 8; j++) {
                int col = nbase + wn + j * 8 + (lane & 3) * 2;
                if (col >= N) continue;
                float c0 = acc[i][j][hf * 2 + 0];
                float c1 = acc[i][j][hf * 2 + 1];
                if (EPI == 0) {
                    split_pair(c0, c1, Ch, Cl, cOff + (size_t)row * ldc + col);
                } else if (EPI == 1) {
                    split_pair(c0 + bias[col], c1 + bias[col + 1], Ch, Cl,
                               (size_t)row * ldc + col);
                } else if (EPI == 2) {
                    float t0 = c0 + bias[col], t1 = c1 + bias[col + 1];
                    t0 = 0.5f * t0 * (1.f + erff(t0 * 0.70710678118654752f));
                    t1 = 0.5f * t1 * (1.f + erff(t1 * 0.70710678118654752f));
                    split_pair(t0, t1, Ch, Cl, (size_t)row * ldc + col);
                } else if (EPI == 3) {
                    size_t idx = (size_t)row * ldc + col;
                    Cf[idx]     = c0 + bias[col]     + Res[idx];
                    Cf[idx + 1] = c1 + bias[col + 1] + Res[idx + 1];
                } else {  // scores: scale + precomputed bf16 bias
                    const bf16* pbz = pb + (size_t)z * SEQ * PBP + (size_t)row * PBP;
                    float* cp = Cf + cOff + (size_t)row * ldc + col;
                    #pragma unroll
                    for (int e = 0; e < 2; e++) {
                        int c = col + e;
                        if (c >= N) continue;
                        cp[e] = (e ? c1 : c0) * SCALEV + __bfloat162float(pbz[c]);
                    }
                }
            }
        }
    }
}

// ---------------- per-layer bias projection: pb[b,h,q,k] = gb.Wb + bb (bf16) ----------------
__global__ void bias_proj(const float* __restrict__ ab, const float* __restrict__ Wb,
                          const float* __restrict__ bb, const float* __restrict__ gvd,
                          bf16* __restrict__ pb) {
    int q = blockIdx.x, b = blockIdx.y;
    int tid = threadIdx.x;
    __shared__ float w[BDIM][NHEADS];
    __shared__ float vv[NHEADS];
    if (tid < BDIM * NHEADS) w[tid / NHEADS][tid % NHEADS] = Wb[tid];
    __syncthreads();
    if (tid < NHEADS) {
        float s = bb[tid];
        #pragma unroll
        for (int d = 0; d < BDIM; d++) s += gvd[d] * w[d][tid];
        vv[tid] = s;
    }
    __syncthreads();
    bool qv = (q >= NNODES);
    for (int k = tid; k < SEQ; k += 256) {
        bool virt = qv || (k >= NNODES);
        float f[8];
        if (!virt) {
            const float* p = ab + (((size_t)b * NNODES + q) * NNODES + k) * BDIM;
            float4 x0 = *(const float4*)p;
            float4 x1 = *(const float4*)(p + 4);
            f[0]=x0.x; f[1]=x0.y; f[2]=x0.z; f[3]=x0.w;
            f[4]=x1.x; f[5]=x1.y; f[6]=x1.z; f[7]=x1.w;
        }
        #pragma unroll
        for (int h = 0; h < NHEADS; h++) {
            float val;
            if (virt) val = vv[h];
            else {
                val = bb[h];
                #pragma unroll
                for (int d = 0; d < BDIM; d++) val += f[d] * w[d][h];
            }
            pb[(((size_t)(b * NHEADS + h)) * SEQ + q) * PBP + k] = __float2bfloat16(val);
        }
    }
}

// ---------------- weight transpose + split: W[K][N] -> oh/ol[N][K] ----------------
__global__ void wsplit_tr(const float* __restrict__ W, bf16* __restrict__ oh,
                          bf16* __restrict__ ol, int K, int N) {
    __shared__ float t[32][33];
    int k0 = blockIdx.y * 32, n0 = blockIdx.x * 32;
    int tx = threadIdx.x, ty = threadIdx.y;
    #pragma unroll
    for (int j = 0; j < 32; j += 8)
        t[ty + j][tx] = W[(size_t)(k0 + ty + j) * N + n0 + tx];
    __syncthreads();
    #pragma unroll
    for (int j = 0; j < 32; j += 8) {
        float v = t[tx][ty + j];
        size_t o = (size_t)(n0 + ty + j) * K + k0 + tx;
        bf16 h = __float2bfloat16(v);
        oh[o] = h;
        ol[o] = __float2bfloat16(v - __bfloat162float(h));
    }
}

// ---------------- V transpose ----------------
__global__ void vtrans_kernel() {
    int z = blockIdx.z, b = z / NHEADS, h = z - b * NHEADS;
    int s0 = blockIdx.x * 32, d0 = blockIdx.y * 32;
    __shared__ bf16 th[32][33], tl[32][33];
    int tx = threadIdx.x, ty = threadIdx.y;
    #pragma unroll
    for (int j = 0; j < 32; j += 8) {
        int s = s0 + ty + j;
        bf16 vh = __float2bfloat16(0.f), vl = vh;
        if (s < SEQ) {
            size_t idx = (size_t)(b * SEQ + s) * HDIM + h * DKH + d0 + tx;
            vh = g_vh[idx]; vl = g_vl[idx];
        }
        th[ty + j][tx] = vh; tl[ty + j][tx] = vl;
    }
    __syncthreads();
    #pragma unroll
    for (int j = 0; j < 32; j += 8) {
        int d = d0 + ty + j, s = s0 + tx;
        if (s < PPITCH) {
            size_t o = ((size_t)z * DKH + d) * PPITCH + s;
            g_vth[o] = th[tx][ty + j];
            g_vtl[o] = tl[tx][ty + j];
        }
    }
}

// ---------------- node encoder + graph token ----------------
__global__ void encode_kernel(const float* __restrict__ x, const float* __restrict__ W,
                              const float* __restrict__ b, const float* __restrict__ gt) {
    int r = blockIdx.x;
    int bb = r / SEQ, s = r % SEQ;
    int tid = threadIdx.x;
    if (s == NNODES) {
        for (int c = tid; c < HDIM; c += 256) g_h[(size_t)r*HDIM + c] = gt[c];
        return;
    }
    __shared__ float xs[INDIM];
    const float* xr = x + ((size_t)bb*NNODES + s)*INDIM;
    if (tid < INDIM) xs[tid] = xr[tid];
    __syncthreads();
    for (int c = tid; c < HDIM; c += 256) {
        float acc = b[c];
        #pragma unroll 8
        for (int k = 0; k < INDIM; k++) acc += xs[k]*W[k*HDIM + c];
        g_h[(size_t)r*HDIM + c] = acc;
    }
}

// ---------------- layernorm: warp-per-row, shfl reductions ----------------
template<bool F32OUT>
__global__ void ln_kernel(const float* __restrict__ in, const float* __restrict__ g,
                          const float* __restrict__ bta, bf16* __restrict__ oh,
                          bf16* __restrict__ ol, float* __restrict__ of) {
    int wid = threadIdx.x >> 5, lane = threadIdx.x & 31;
    int r = blockIdx.x * 8 + wid;
    if (r >= ROWS) return;
    const float4* row = (const float4*)(in + (size_t)r * HDIM);
    const float4* g4 = (const float4*)g;
    const float4* b4 = (const float4*)bta;
    float4 v[6];
    float s = 0.f;
    #pragma unroll
    for (int i = 0; i < 6; i++) {
        v[i] = row[lane + i * 32];
        s += v[i].x + v[i].y + v[i].z + v[i].w;
    }
    s = wred_sum(s);
    float mean = s * (1.f / HDIM);
    float vs = 0.f;
    #pragma unroll
    for (int i = 0; i < 6; i++) {
        float d0 = v[i].x - mean, d1 = v[i].y - mean, d2 = v[i].z - mean, d3 = v[i].w - mean;
        vs += d0*d0 + d1*d1 + d2*d2 + d3*d3;
    }
    vs = wred_sum(vs);
    float rstd = rsqrtf(vs * (1.f / HDIM) + EPSV);
    #pragma unroll
    for (int i = 0; i < 6; i++) {
        int c4 = lane + i * 32;
        float4 gg = g4[c4], bb = b4[c4];
        float o0 = (v[i].x - mean) * rstd * gg.x + bb.x;
        float o1 = (v[i].y - mean) * rstd * gg.y + bb.y;
        float o2 = (v[i].z - mean) * rstd * gg.z + bb.z;
        float o3 = (v[i].w - mean) * rstd * gg.w + bb.w;
        size_t idx = (size_t)r * HDIM + c4 * 4;
        split_pair(o0, o1, oh, ol, idx);
        split_pair(o2, o3, oh, ol, idx + 2);
        if (F32OUT) *(float4*)(of + idx) = make_float4(o0, o1, o2, o3);
    }
}

// ---------------- softmax: warp-per-row -> split bf16 probs ----------------
__global__ void softmax_kernel() {
    int wid = threadIdx.x >> 5, lane = threadIdx.x & 31;
    size_t row = (size_t)blockIdx.x * 8 + wid;
    if (row >= (size_t)BATCH * NHEADS * SEQ) return;
    float* p = g_sc + row * SEQP;
    float e[15];
    float m = -1e30f;
    #pragma unroll
    for (int i = 0; i < 15; i++) {
        int k = lane + i * 32;
        e[i] = (k < SEQ) ? p[k] : -1e30f;
        m = fmaxf(m, e[i]);
    }
    m = wred_max(m);
    float s = 0.f;
    #pragma unroll
    for (int i = 0; i < 15; i++) {
        int k = lane + i * 32;
        e[i] = (k < SEQ) ? __expf(e[i] - m) : 0.f;
        s += e[i];
    }
    s = wred_sum(s);
    float inv = 1.f / s;
    bf16* ph = g_ph + row * PPITCH;
    bf16* pl = g_pl + row * PPITCH;
    #pragma unroll
    for (int i = 0; i < 15; i++) {
        int k = lane + i * 32;
        if (k >= PPITCH) continue;
        float v = e[i] * inv;              // zero for pad/oob lanes
        bf16 h = __float2bfloat16(v);
        ph[k] = h;
        pl[k] = __float2bfloat16(v - __bfloat162float(h));
    }
}

// ---------------- readout ----------------
__global__ void readout_kernel(const float* __restrict__ W, const float* __restrict__ bo,
                               float* __restrict__ out) {
    int b = blockIdx.x;
    int tid = threadIdx.x;
    const float* y = g_y + (size_t)(b*SEQ)*HDIM;
    __shared__ float red[256];
    __shared__ float logits[OUTD];
    float acc[OUTD];
    #pragma unroll
    for (int o = 0; o < OUTD; o++) acc[o] = 0.f;
    for (int k = tid; k < HDIM; k += 256) {
        float yv = y[k];
        #pragma unroll
        for (int o = 0; o < OUTD; o++) acc[o] += yv*W[k*OUTD + o];
    }
    for (int o = 0; o < OUTD; o++) {
        red[tid] = acc[o]; __syncthreads();
        for (int s = 128; s > 0; s >>= 1) { if (tid < s) red[tid] += red[tid+s]; __syncthreads(); }
        if (tid == 0) logits[o] = red[0] + bo[o];
        __syncthreads();
    }
    if (tid == 0) {
        float m = -1e30f;
        for (int o = 0; o < OUTD; o++) m = fmaxf(m, logits[o]);
        float s = 0.f;
        for (int o = 0; o < OUTD; o++) s += expf(logits[o]-m);
        float lse = m + logf(s);
        for (int o = 0; o < OUTD; o++) out[b*OUTD + o] = logits[o] - lse;
    }
}

extern "C" void kernel_launch(void* const* d_in, const int* in_sizes, int n_in,
                              void* d_out, int out_size) {
    const float* attn_bias = (const float*)d_in[0];
    const float* x         = (const float*)d_in[1];
    const float* enc_W     = (const float*)d_in[2];
    const float* enc_b     = (const float*)d_in[3];
    const float* gtok      = (const float*)d_in[4];
    const float* gvd       = (const float*)d_in[5];
    const float* ln1_g     = (const float*)d_in[6];
    const float* ln1_b     = (const float*)d_in[7];
    const float* Wq        = (const float*)d_in[8];
    const float* bq        = (const float*)d_in[9];
    const float* Wk        = (const float*)d_in[10];
    const float* bk        = (const float*)d_in[11];
    const float* Wv        = (const float*)d_in[12];
    const float* bv        = (const float*)d_in[13];
    const float* Wbias     = (const float*)d_in[14];
    const float* bbias     = (const float*)d_in[15];
    const float* Wo        = (const float*)d_in[16];
    const float* bo        = (const float*)d_in[17];
    const float* ln2_g     = (const float*)d_in[18];
    const float* ln2_b     = (const float*)d_in[19];
    const float* W1        = (const float*)d_in[20];
    const float* b1        = (const float*)d_in[21];
    const float* W2        = (const float*)d_in[22];
    const float* b2        = (const float*)d_in[23];
    const float* fln_g     = (const float*)d_in[24];
    const float* fln_b     = (const float*)d_in[25];
    const float* out_W     = (const float*)d_in[26];
    const float* out_b     = (const float*)d_in[27];

    float *h_, *y_, *sc_;
    bf16 *yh_, *yl_, *qh_, *ql_, *kh_, *kl_, *vh_, *vl_, *oh_, *ol_, *fh_, *fl_;
    bf16 *ph_, *pl_, *vth_, *vtl_, *wh_, *wl_, *pb_;
    cudaGetSymbolAddress((void**)&h_,  g_h);
    cudaGetSymbolAddress((void**)&y_,  g_y);
    cudaGetSymbolAddress((void**)&sc_, g_sc);
    cudaGetSymbolAddress((void**)&yh_, g_yh);  cudaGetSymbolAddress((void**)&yl_, g_yl);
    cudaGetSymbolAddress((void**)&qh_, g_qh);  cudaGetSymbolAddress((void**)&ql_, g_ql);
    cudaGetSymbolAddress((void**)&kh_, g_kh);  cudaGetSymbolAddress((void**)&kl_, g_kl);
    cudaGetSymbolAddress((void**)&vh_, g_vh);  cudaGetSymbolAddress((void**)&vl_, g_vl);
    cudaGetSymbolAddress((void**)&oh_, g_oh);  cudaGetSymbolAddress((void**)&ol_, g_ol);
    cudaGetSymbolAddress((void**)&fh_, g_fh);  cudaGetSymbolAddress((void**)&fl_, g_fl);
    cudaGetSymbolAddress((void**)&ph_, g_ph);  cudaGetSymbolAddress((void**)&pl_, g_pl);
    cudaGetSymbolAddress((void**)&vth_, g_vth); cudaGetSymbolAddress((void**)&vtl_, g_vtl);
    cudaGetSymbolAddress((void**)&wh_, g_wh);  cudaGetSymbolAddress((void**)&wl_, g_wl);
    cudaGetSymbolAddress((void**)&pb_, g_pb);

    cudaFuncSetAttribute(mma2<0,2>, cudaFuncAttributeMaxDynamicSharedMemorySize, SMEM_MMA);
    cudaFuncSetAttribute(mma2<1,0>, cudaFuncAttributeMaxDynamicSharedMemorySize, SMEM_MMA);
    cudaFuncSetAttribute(mma2<2,0>, cudaFuncAttributeMaxDynamicSharedMemorySize, SMEM_MMA);
    cudaFuncSetAttribute(mma2<3,0>, cudaFuncAttributeMaxDynamicSharedMemorySize, SMEM_MMA);
    cudaFuncSetAttribute(mma2<4,1>, cudaFuncAttributeMaxDynamicSharedMemorySize, SMEM_MMA);

    // ---- weight pre-split (transpose to [N][K]) ----
    const dim3 wb32(32, 8);
    for (int i = 0; i < NLAYER; i++) {
        size_t off = (size_t)i * LSTR;
        wsplit_tr<<<dim3(HDIM/32, HDIM/32), wb32>>>(Wq + i*HH, wh_ + off,        wl_ + off,        HDIM, HDIM);
        wsplit_tr<<<dim3(HDIM/32, HDIM/32), wb32>>>(Wk + i*HH, wh_ + off + HH,   wl_ + off + HH,   HDIM, HDIM);
        wsplit_tr<<<dim3(HDIM/32, HDIM/32), wb32>>>(Wv + i*HH, wh_ + off + 2*HH, wl_ + off + 2*HH, HDIM, HDIM);
        wsplit_tr<<<dim3(HDIM/32, HDIM/32), wb32>>>(Wo + i*HH, wh_ + off + 3*HH, wl_ + off + 3*HH, HDIM, HDIM);
        wsplit_tr<<<dim3(FFND/32, HDIM/32), wb32>>>(W1 + i*HF, wh_ + off + 4*HH, wl_ + off + 4*HH, HDIM, FFND);
        wsplit_tr<<<dim3(HDIM/32, FFND/32), wb32>>>(W2 + i*HF, wh_ + off + 4*HH + HF, wl_ + off + 4*HH + HF, FFND, HDIM);
    }

    encode_kernel<<<ROWS, 256>>>(x, enc_W, enc_b, gtok);

    const dim3 ggrid(HDIM/128, (ROWS + 127)/128);          // 6,57
    const dim3 fgrid(FFND/128, (ROWS + 127)/128);          // 24,57
    const dim3 sgrid((SEQ+127)/128, (SEQ+127)/128, BATCH*NHEADS);  // 4,4,192
    const dim3 avgrid(1, (SEQ+127)/128, BATCH*NHEADS);
    const dim3 vtgrid((SEQ+31)/32, DKH/32, BATCH*NHEADS);  // 15,2,192
    const int lnGrid = (ROWS + 7) / 8;
    const int smGrid = (BATCH*NHEADS*SEQ + 7) / 8;

    for (int i = 0; i < NLAYER; i++) {
        size_t off = (size_t)i * LSTR;
        bias_proj<<<dim3(SEQ, BATCH), 256>>>(attn_bias, Wbias + i*BDIM*NHEADS,
                                             bbias + i*NHEADS, gvd, pb_);
        ln_kernel<false><<<lnGrid, 256>>>(h_, ln1_g + i*HDIM, ln1_b + i*HDIM, yh_, yl_, nullptr);
        mma2<1,0><<<ggrid, 256, SMEM_MMA>>>(yh_, yl_, HDIM, wh_ + off, wl_ + off, HDIM,
            bq + i*HDIM, nullptr, qh_, ql_, nullptr, ROWS, HDIM, HDIM, HDIM, nullptr);
        mma2<1,0><<<ggrid, 256, SMEM_MMA>>>(yh_, yl_, HDIM, wh_ + off + HH, wl_ + off + HH, HDIM,
            bk + i*HDIM, nullptr, kh_, kl_, nullptr, ROWS, HDIM, HDIM, HDIM, nullptr);
        mma2<1,0><<<ggrid, 256, SMEM_MMA>>>(yh_, yl_, HDIM, wh_ + off + 2*HH, wl_ + off + 2*HH, HDIM,
            bv + i*HDIM, nullptr, vh_, vl_, nullptr, ROWS, HDIM, HDIM, HDIM, nullptr);
        vtrans_kernel<<<vtgrid, wb32>>>();
        mma2<4,1><<<sgrid, 256, SMEM_MMA>>>(qh_, ql_, HDIM, kh_, kl_, HDIM,
            nullptr, sc_, nullptr, nullptr, nullptr, SEQ, SEQ, DKH, SEQP, pb_);
        softmax_kernel<<<smGrid, 256>>>();
        mma2<0,2><<<avgrid, 256, SMEM_MMA>>>(ph_, pl_, PPITCH, vth_, vtl_, PPITCH,
            nullptr, nullptr, oh_, ol_, nullptr, SEQ, DKH, SEQ, HDIM, nullptr);
        mma2<3,0><<<ggrid, 256, SMEM_MMA>>>(oh_, ol_, HDIM, wh_ + off + 3*HH, wl_ + off + 3*HH, HDIM,
            bo + i*HDIM, h_, nullptr, nullptr, h_, ROWS, HDIM, HDIM, HDIM, nullptr);
        ln_kernel<false><<<lnGrid, 256>>>(h_, ln2_g + i*HDIM, ln2_b + i*HDIM, yh_, yl_, nullptr);
        mma2<2,0><<<fgrid, 256, SMEM_MMA>>>(yh_, yl_, HDIM, wh_ + off + 4*HH, wl_ + off + 4*HH, HDIM,
            b1 + i*FFND, nullptr, fh_, fl_, nullptr, ROWS, FFND, HDIM, FFND, nullptr);
        mma2<3,0><<<ggrid, 256, SMEM_MMA>>>(fh_, fl_, FFND, wh_ + off + 4*HH + HF, wl_ + off + 4*HH + HF, FFND,
            b2 + i*HDIM, h_, nullptr, nullptr, h_, ROWS, HDIM, FFND, HDIM, nullptr);
    }

    ln_kernel<true><<<lnGrid, 256>>>(h_, fln_g, fln_b, yh_, yl_, y_);
    readout_kernel<<<BATCH, 256>>>(out_W, out_b, (float*)d_out);
}

// round 7
// speedup vs baseline: 3.7051x; 1.0807x over previous
#include <cuda_runtime.h>
#include <cuda_bf16.h>
#include <math.h>
#include <stdint.h>
#include <string.h>

#define BATCH   16
#define NNODES  448
#define SEQ     449
#define SEQP    452            /* fp32 score row pitch */
#define PPITCH  456            /* bf16 probs / vt row pitch (mult of 8) */
#define PBP     456            /* bias-projection row pitch */
#define HDIM    768
#define QKVD    (3*HDIM)       /* 2304 */
#define NHEADS  12
#define DKH     64
#define FFND    3072
#define BDIM    8
#define NLAYER  6
#define OUTD    10
#define INDIM   128
#define EPSV    1e-5f
#define SCALEV  0.125f
#define ROWS    (BATCH*SEQ)   /* 7184 */

#define HH      ((size_t)HDIM*HDIM)
#define HF      ((size_t)HDIM*FFND)
#define LSTR    (4*HH + 2*HF)
#define SMEM_MMA 81920

typedef __nv_bfloat16 bf16;

// ---------------- scratch (device globals: alloc-free) ----------------
__device__ float g_h [(size_t)ROWS*HDIM];
__device__ float g_y [(size_t)ROWS*HDIM];
__device__ float g_sc[(size_t)BATCH*NHEADS*SEQ*SEQP];
__device__ float g_bqkv[(size_t)NLAYER*QKVD];

__device__ __align__(16) bf16 g_yh[(size_t)ROWS*HDIM];
__device__ __align__(16) bf16 g_yl[(size_t)ROWS*HDIM];
__device__ __align__(16) bf16 g_qkvh[(size_t)ROWS*QKVD];
__device__ __align__(16) bf16 g_qkvl[(size_t)ROWS*QKVD];
__device__ __align__(16) bf16 g_oh[(size_t)ROWS*HDIM];
__device__ __align__(16) bf16 g_ol[(size_t)ROWS*HDIM];
__device__ __align__(16) bf16 g_fh[(size_t)ROWS*FFND];
__device__ __align__(16) bf16 g_fl[(size_t)ROWS*FFND];
__device__ __align__(16) bf16 g_ph[(size_t)BATCH*NHEADS*SEQ*PPITCH];
__device__ __align__(16) bf16 g_pl[(size_t)BATCH*NHEADS*SEQ*PPITCH];
__device__ __align__(16) bf16 g_vth[(size_t)BATCH*NHEADS*DKH*PPITCH];
__device__ __align__(16) bf16 g_vtl[(size_t)BATCH*NHEADS*DKH*PPITCH];
__device__ __align__(16) bf16 g_wh[(size_t)NLAYER*LSTR];
__device__ __align__(16) bf16 g_wl[(size_t)NLAYER*LSTR];
__device__ __align__(16) bf16 g_pb[(size_t)BATCH*NHEADS*SEQ*PBP];

// ---------------- helpers ----------------
__device__ __forceinline__ uint32_t smem_u32(const void* p) {
    uint32_t a;
    asm("{ .reg .u64 t; cvta.to.shared.u64 t, %1; cvt.u32.u64 %0, t; }" : "=r"(a) : "l"(p));
    return a;
}
__device__ __forceinline__ uint32_t packbf(bf16 a, bf16 b) {
    __nv_bfloat162 t; t.x = a; t.y = b;
    uint32_t u; memcpy(&u, &t, 4); return u;
}
__device__ __forceinline__ void split_pair(float v0, float v1, bf16* H, bf16* L, size_t idx) {
    bf16 h0 = __float2bfloat16(v0), h1 = __float2bfloat16(v1);
    bf16 l0 = __float2bfloat16(v0 - __bfloat162float(h0));
    bf16 l1 = __float2bfloat16(v1 - __bfloat162float(h1));
    *(uint32_t*)(H + idx) = packbf(h0, h1);
    *(uint32_t*)(L + idx) = packbf(l0, l1);
}
__device__ __forceinline__ void cpa(uint32_t dst, const bf16* src, int bytes) {
    asm volatile("cp.async.cg.shared.global [%0], [%1], 16, %2;"
                 :: "r"(dst), "l"(__cvta_generic_to_global(src)), "r"(bytes));
}
#define CP_COMMIT() asm volatile("cp.async.commit_group;" ::: "memory")
#define CP_WAIT0()  asm volatile("cp.async.wait_group 0;" ::: "memory")
#define CP_WAIT1()  asm volatile("cp.async.wait_group 1;" ::: "memory")

#define LDMX4(r0,r1,r2,r3,addr) \
    asm volatile("ldmatrix.sync.aligned.m8n8.x4.shared.b16 {%0,%1,%2,%3}, [%4];" \
        : "=r"(r0),"=r"(r1),"=r"(r2),"=r"(r3) : "r"(addr))

#define MMA16816(c,a,b) \
    asm volatile("mma.sync.aligned.m16n8k16.row.col.f32.bf16.bf16.f32 " \
        "{%0,%1,%2,%3},{%4,%5,%6,%7},{%8,%9},{%0,%1,%2,%3};" \
        : "+f"((c)[0]),"+f"((c)[1]),"+f"((c)[2]),"+f"((c)[3]) \
        : "r"((a)[0]),"r"((a)[1]),"r"((a)[2]),"r"((a)[3]),"r"((b)[0]),"r"((b)[1]))

__device__ __forceinline__ float wred_sum(float v) {
    #pragma unroll
    for (int o = 16; o > 0; o >>= 1) v += __shfl_xor_sync(0xffffffffu, v, o);
    return v;
}
__device__ __forceinline__ float wred_max(float v) {
    #pragma unroll
    for (int o = 16; o > 0; o >>= 1) v = fmaxf(v, __shfl_xor_sync(0xffffffffu, v, o));
    return v;
}

// ============== bf16x3 MMA GEMM, pre-split operands, cp.async pipelined ==============
// EPI: 0 split out (AV), 1 bias+split out (QKV), 2 bias+gelu+split (FFN1),
//      3 bias+res fp32 (Wo/FFN2), 4 scores fp32 (scale + precomputed bf16 bias)
// BMODE: 0 none, 1 scores, 2 AV.  TN: CTA tile width (128 or 64).
template<int EPI, int BMODE, int TN>
__global__ void __launch_bounds__(256, 2)
mma2(const bf16* __restrict__ Ah, const bf16* __restrict__ Al, int lda,
     const bf16* __restrict__ Bh, const bf16* __restrict__ Bl, int ldb,
     const float* __restrict__ bias,
     float* __restrict__ Cf, bf16* __restrict__ Ch, bf16* __restrict__ Cl,
     const float* __restrict__ Res,
     int M, int N, int K, int ldc,
     const bf16* __restrict__ pb) {
    extern __shared__ __align__(16) char smem[];
    constexpr int NJ = TN / 16;          // per-warp N chunks of 8 (8 or 4)
    const int tid = threadIdx.x, wid = tid >> 5, lane = tid & 31;
    const int mbase = blockIdx.y * 128, nbase = blockIdx.x * TN;
    const int z = blockIdx.z;

    size_t aOff = 0, bOff = 0, cOff = 0;
    if (BMODE == 1) {
        int b = z / NHEADS, h = z - b * NHEADS;
        aOff = (size_t)b * SEQ * QKVD + h * DKH;          // Q slice
        bOff = aOff + HDIM;                               // K slice
        cOff = (size_t)z * SEQ * SEQP;
    } else if (BMODE == 2) {
        int b = z / NHEADS, h = z - b * NHEADS;
        aOff = (size_t)z * SEQ * PPITCH;
        bOff = (size_t)z * DKH * PPITCH;
        cOff = (size_t)b * SEQ * HDIM + h * DKH;
    }

    const uint32_t sbase = smem_u32(smem);
    float acc[2][NJ][4];
    #pragma unroll
    for (int i = 0; i < 2; i++)
        #pragma unroll
        for (int j = 0; j < NJ; j++)
            #pragma unroll
            for (int e = 0; e < 4; e++) acc[i][j][e] = 0.f;

    const int wm = (wid & 3) * 32, wn = (wid >> 2) * (TN / 2);
    const int nkc = (K + 31) >> 5;

    auto stage = [&](int buf, int kc) {
        uint32_t sb0 = sbase + buf * 40960;
        #pragma unroll
        for (int m = 0; m < 2; m++) {
            int c = tid + m * 256;
            int row = c >> 2, k8 = c & 3;
            int kpos = kc + k8 * 8;
            int kb = K - kpos;
            int kbytes = kb <= 0 ? 0 : (kb >= 8 ? 16 : kb * 2);
            int kposc = kb <= 0 ? 0 : kpos;
            uint32_t doff = (uint32_t)row * 80u + (uint32_t)k8 * 16u;
            {
                int gr = mbase + row;
                int ok = (gr < M) ? kbytes : 0;
                int grc = (gr < M) ? gr : 0;
                size_t gi = aOff + (size_t)grc * lda + kposc;
                cpa(sb0 + doff, Ah + gi, ok);
                cpa(sb0 + 10240 + doff, Al + gi, ok);
            }
            {
                int gn = nbase + row;
                int ok = (gn < N && row < TN) ? kbytes : 0;
                int gnc = (gn < N && row < TN) ? gn : 0;
                size_t gi = bOff + (size_t)gnc * ldb + kposc;
                cpa(sb0 + 20480 + doff, Bh + gi, ok);
                cpa(sb0 + 30720 + doff, Bl + gi, ok);
            }
        }
        CP_COMMIT();
    };

    stage(0, 0);
    for (int ic = 0; ic < nkc; ic++) {
        int buf = ic & 1;
        if (ic + 1 < nkc) { stage(buf ^ 1, (ic + 1) * 32); CP_WAIT1(); }
        else              { CP_WAIT0(); }
        __syncthreads();

        const uint32_t aHb = sbase + buf * 40960, aLb = aHb + 10240;
        const uint32_t bHb = aHb + 20480, bLb = aHb + 30720;
        #pragma unroll
        for (int ks = 0; ks < 2; ks++) {
            uint32_t bh[NJ][2], bl[NJ][2];
            int bn = ((lane >> 4) << 3) + (lane & 7);
            int bkh = (lane >> 3) & 1;
            #pragma unroll
            for (int g = 0; g < NJ / 2; g++) {
                uint32_t off = (uint32_t)(wn + g * 16 + bn) * 80u + (uint32_t)(ks * 16 + bkh * 8) * 2u;
                LDMX4(bh[2*g][0], bh[2*g][1], bh[2*g+1][0], bh[2*g+1][1], bHb + off);
                LDMX4(bl[2*g][0], bl[2*g][1], bl[2*g+1][0], bl[2*g+1][1], bLb + off);
            }
            #pragma unroll
            for (int i = 0; i < 2; i++) {
                int ar = wm + i * 16 + (lane & 15);
                uint32_t off = (uint32_t)ar * 80u + (uint32_t)(ks * 16 + (lane >> 4) * 8) * 2u;
                uint32_t ah[4], al[4];
                LDMX4(ah[0], ah[1], ah[2], ah[3], aHb + off);
                LDMX4(al[0], al[1], al[2], al[3], aLb + off);
                #pragma unroll
                for (int j = 0; j < NJ; j++) {
                    MMA16816(acc[i][j], ah, bh[j]);
                    MMA16816(acc[i][j], ah, bl[j]);
                    MMA16816(acc[i][j], al, bh[j]);
                }
            }
        }
        __syncthreads();
    }

    // ---- epilogue ----
    #pragma unroll
    for (int i = 0; i < 2; i++) {
        #pragma unroll
        for (int hf = 0; hf < 2; hf++) {
            int row = mbase + wm + i * 16 + (lane >> 2) + hf * 8;
            if (row >= M) continue;
            #pragma unroll
            for (int j = 0; j < NJ; j++) {
                int col = nbase + wn + j * 8 + (lane & 3) * 2;
                if (col >= N) continue;
                float c0 = acc[i][j][hf * 2 + 0];
                float c1 = acc[i][j][hf * 2 + 1];
                if (EPI == 0) {
                    split_pair(c0, c1, Ch, Cl, cOff + (size_t)row * ldc + col);
                } else if (EPI == 1) {
                    split_pair(c0 + bias[col], c1 + bias[col + 1], Ch, Cl,
                               (size_t)row * ldc + col);
                } else if (EPI == 2) {
                    float t0 = c0 + bias[col], t1 = c1 + bias[col + 1];
                    t0 = 0.5f * t0 * (1.f + erff(t0 * 0.70710678118654752f));
                    t1 = 0.5f * t1 * (1.f + erff(t1 * 0.70710678118654752f));
                    split_pair(t0, t1, Ch, Cl, (size_t)row * ldc + col);
                } else if (EPI == 3) {
                    size_t idx = (size_t)row * ldc + col;
                    Cf[idx]     = c0 + bias[col]     + Res[idx];
                    Cf[idx + 1] = c1 + bias[col + 1] + Res[idx + 1];
                } else {  // scores: scale + precomputed bf16 bias
                    const bf16* pbz = pb + (size_t)z * SEQ * PBP + (size_t)row * PBP;
                    float* cp = Cf + cOff + (size_t)row * ldc + col;
                    #pragma unroll
                    for (int e = 0; e < 2; e++) {
                        int c = col + e;
                        if (c >= N) continue;
                        cp[e] = (e ? c1 : c0) * SCALEV + __bfloat162float(pbz[c]);
                    }
                }
            }
        }
    }
}

// ---------------- per-layer bias projection ----------------
__global__ void bias_proj(const float* __restrict__ ab, const float* __restrict__ Wb,
                          const float* __restrict__ bb, const float* __restrict__ gvd,
                          bf16* __restrict__ pb) {
    int q = blockIdx.x, b = blockIdx.y;
    int tid = threadIdx.x;
    __shared__ float w[BDIM][NHEADS];
    __shared__ float vv[NHEADS];
    if (tid < BDIM * NHEADS) w[tid / NHEADS][tid % NHEADS] = Wb[tid];
    __syncthreads();
    if (tid < NHEADS) {
        float s = bb[tid];
        #pragma unroll
        for (int d = 0; d < BDIM; d++) s += gvd[d] * w[d][tid];
        vv[tid] = s;
    }
    __syncthreads();
    bool qv = (q >= NNODES);
    for (int k = tid; k < SEQ; k += 256) {
        bool virt = qv || (k >= NNODES);
        float f[8];
        if (!virt) {
            const float* p = ab + (((size_t)b * NNODES + q) * NNODES + k) * BDIM;
            float4 x0 = *(const float4*)p;
            float4 x1 = *(const float4*)(p + 4);
            f[0]=x0.x; f[1]=x0.y; f[2]=x0.z; f[3]=x0.w;
            f[4]=x1.x; f[5]=x1.y; f[6]=x1.z; f[7]=x1.w;
        }
        #pragma unroll
        for (int h = 0; h < NHEADS; h++) {
            float val;
            if (virt) val = vv[h];
            else {
                val = bb[h];
                #pragma unroll
                for (int d = 0; d < BDIM; d++) val += f[d] * w[d][h];
            }
            pb[(((size_t)(b * NHEADS + h)) * SEQ + q) * PBP + k] = __float2bfloat16(val);
        }
    }
}

// ---------------- weight transpose + split, batched over layers ----------------
// W[z*sin + k*N + n] -> out[z*LSTR + obase + n*K + k] (hi/lo)
__global__ void wsplit_tr(const float* __restrict__ W, bf16* __restrict__ oh,
                          bf16* __restrict__ ol, int K, int N,
                          size_t sin, size_t obase) {
    __shared__ float t[32][33];
    int k0 = blockIdx.y * 32, n0 = blockIdx.x * 32;
    size_t iz = (size_t)blockIdx.z * sin;
    size_t oz = (size_t)blockIdx.z * LSTR + obase;
    int tx = threadIdx.x, ty = threadIdx.y;
    #pragma unroll
    for (int j = 0; j < 32; j += 8)
        t[ty + j][tx] = W[iz + (size_t)(k0 + ty + j) * N + n0 + tx];
    __syncthreads();
    #pragma unroll
    for (int j = 0; j < 32; j += 8) {
        float v = t[tx][ty + j];
        size_t o = oz + (size_t)(n0 + ty + j) * K + k0 + tx;
        bf16 h = __float2bfloat16(v);
        oh[o] = h;
        ol[o] = __float2bfloat16(v - __bfloat162float(h));
    }
}

// ---------------- pack QKV bias ----------------
__global__ void pack_bias(const float* __restrict__ bq, const float* __restrict__ bk,
                          const float* __restrict__ bv, float* __restrict__ o) {
    int i = blockIdx.x * 256 + threadIdx.x;
    int z = i / QKVD, c = i % QKVD;
    if (z >= NLAYER) return;
    float v;
    if (c < HDIM)            v = bq[z * HDIM + c];
    else if (c < 2 * HDIM)   v = bk[z * HDIM + c - HDIM];
    else                     v = bv[z * HDIM + c - 2 * HDIM];
    o[i] = v;
}

// ---------------- V transpose (from combined qkv buffer) ----------------
__global__ void vtrans_kernel() {
    int z = blockIdx.z, b = z / NHEADS, h = z - b * NHEADS;
    int s0 = blockIdx.x * 32, d0 = blockIdx.y * 32;
    __shared__ bf16 th[32][33], tl[32][33];
    int tx = threadIdx.x, ty = threadIdx.y;
    #pragma unroll
    for (int j = 0; j < 32; j += 8) {
        int s = s0 + ty + j;
        bf16 vh = __float2bfloat16(0.f), vl = vh;
        if (s < SEQ) {
            size_t idx = (size_t)(b * SEQ + s) * QKVD + 2 * HDIM + h * DKH + d0 + tx;
            vh = g_qkvh[idx]; vl = g_qkvl[idx];
        }
        th[ty + j][tx] = vh; tl[ty + j][tx] = vl;
    }
    __syncthreads();
    #pragma unroll
    for (int j = 0; j < 32; j += 8) {
        int d = d0 + ty + j, s = s0 + tx;
        if (s < PPITCH) {
            size_t o = ((size_t)z * DKH + d) * PPITCH + s;
            g_vth[o] = th[tx][ty + j];
            g_vtl[o] = tl[tx][ty + j];
        }
    }
}

// ---------------- node encoder + graph token ----------------
__global__ void encode_kernel(const float* __restrict__ x, const float* __restrict__ W,
                              const float* __restrict__ b, const float* __restrict__ gt) {
    int r = blockIdx.x;
    int bb = r / SEQ, s = r % SEQ;
    int tid = threadIdx.x;
    if (s == NNODES) {
        for (int c = tid; c < HDIM; c += 256) g_h[(size_t)r*HDIM + c] = gt[c];
        return;
    }
    __shared__ float xs[INDIM];
    const float* xr = x + ((size_t)bb*NNODES + s)*INDIM;
    if (tid < INDIM) xs[tid] = xr[tid];
    __syncthreads();
    for (int c = tid; c < HDIM; c += 256) {
        float acc = b[c];
        #pragma unroll 8
        for (int k = 0; k < INDIM; k++) acc += xs[k]*W[k*HDIM + c];
        g_h[(size_t)r*HDIM + c] = acc;
    }
}

// ---------------- layernorm: warp-per-row ----------------
template<bool F32OUT>
__global__ void ln_kernel(const float* __restrict__ in, const float* __restrict__ g,
                          const float* __restrict__ bta, bf16* __restrict__ oh,
                          bf16* __restrict__ ol, float* __restrict__ of) {
    int wid = threadIdx.x >> 5, lane = threadIdx.x & 31;
    int r = blockIdx.x * 8 + wid;
    if (r >= ROWS) return;
    const float4* row = (const float4*)(in + (size_t)r * HDIM);
    const float4* g4 = (const float4*)g;
    const float4* b4 = (const float4*)bta;
    float4 v[6];
    float s = 0.f;
    #pragma unroll
    for (int i = 0; i < 6; i++) {
        v[i] = row[lane + i * 32];
        s += v[i].x + v[i].y + v[i].z + v[i].w;
    }
    s = wred_sum(s);
    float mean = s * (1.f / HDIM);
    float vs = 0.f;
    #pragma unroll
    for (int i = 0; i < 6; i++) {
        float d0 = v[i].x - mean, d1 = v[i].y - mean, d2 = v[i].z - mean, d3 = v[i].w - mean;
        vs += d0*d0 + d1*d1 + d2*d2 + d3*d3;
    }
    vs = wred_sum(vs);
    float rstd = rsqrtf(vs * (1.f / HDIM) + EPSV);
    #pragma unroll
    for (int i = 0; i < 6; i++) {
        int c4 = lane + i * 32;
        float4 gg = g4[c4], bb = b4[c4];
        float o0 = (v[i].x - mean) * rstd * gg.x + bb.x;
        float o1 = (v[i].y - mean) * rstd * gg.y + bb.y;
        float o2 = (v[i].z - mean) * rstd * gg.z + bb.z;
        float o3 = (v[i].w - mean) * rstd * gg.w + bb.w;
        size_t idx = (size_t)r * HDIM + c4 * 4;
        split_pair(o0, o1, oh, ol, idx);
        split_pair(o2, o3, oh, ol, idx + 2);
        if (F32OUT) *(float4*)(of + idx) = make_float4(o0, o1, o2, o3);
    }
}

// ---------------- softmax: warp-per-row -> split bf16 probs ----------------
__global__ void softmax_kernel() {
    int wid = threadIdx.x >> 5, lane = threadIdx.x & 31;
    size_t row = (size_t)blockIdx.x * 8 + wid;
    if (row >= (size_t)BATCH * NHEADS * SEQ) return;
    float* p = g_sc + row * SEQP;
    float e[15];
    float m = -1e30f;
    #pragma unroll
    for (int i = 0; i < 15; i++) {
        int k = lane + i * 32;
        e[i] = (k < SEQ) ? p[k] : -1e30f;
        m = fmaxf(m, e[i]);
    }
    m = wred_max(m);
    float s = 0.f;
    #pragma unroll
    for (int i = 0; i < 15; i++) {
        int k = lane + i * 32;
        e[i] = (k < SEQ) ? __expf(e[i] - m) : 0.f;
        s += e[i];
    }
    s = wred_sum(s);
    float inv = 1.f / s;
    bf16* ph = g_ph + row * PPITCH;
    bf16* pl = g_pl + row * PPITCH;
    #pragma unroll
    for (int i = 0; i < 15; i++) {
        int k = lane + i * 32;
        if (k >= PPITCH) continue;
        float v = e[i] * inv;
        bf16 h = __float2bfloat16(v);
        ph[k] = h;
        pl[k] = __float2bfloat16(v - __bfloat162float(h));
    }
}

// ---------------- readout ----------------
__global__ void readout_kernel(const float* __restrict__ W, const float* __restrict__ bo,
                               float* __restrict__ out) {
    int b = blockIdx.x;
    int tid = threadIdx.x;
    const float* y = g_y + (size_t)(b*SEQ)*HDIM;
    __shared__ float red[256];
    __shared__ float logits[OUTD];
    float acc[OUTD];
    #pragma unroll
    for (int o = 0; o < OUTD; o++) acc[o] = 0.f;
    for (int k = tid; k < HDIM; k += 256) {
        float yv = y[k];
        #pragma unroll
        for (int o = 0; o < OUTD; o++) acc[o] += yv*W[k*OUTD + o];
    }
    for (int o = 0; o < OUTD; o++) {
        red[tid] = acc[o]; __syncthreads();
        for (int s = 128; s > 0; s >>= 1) { if (tid < s) red[tid] += red[tid+s]; __syncthreads(); }
        if (tid == 0) logits[o] = red[0] + bo[o];
        __syncthreads();
    }
    if (tid == 0) {
        float m = -1e30f;
        for (int o = 0; o < OUTD; o++) m = fmaxf(m, logits[o]);
        float s = 0.f;
        for (int o = 0; o < OUTD; o++) s += expf(logits[o]-m);
        float lse = m + logf(s);
        for (int o = 0; o < OUTD; o++) out[b*OUTD + o] = logits[o] - lse;
    }
}

extern "C" void kernel_launch(void* const* d_in, const int* in_sizes, int n_in,
                              void* d_out, int out_size) {
    const float* attn_bias = (const float*)d_in[0];
    const float* x         = (const float*)d_in[1];
    const float* enc_W     = (const float*)d_in[2];
    const float* enc_b     = (const float*)d_in[3];
    const float* gtok      = (const float*)d_in[4];
    const float* gvd       = (const float*)d_in[5];
    const float* ln1_g     = (const float*)d_in[6];
    const float* ln1_b     = (const float*)d_in[7];
    const float* Wq        = (const float*)d_in[8];
    const float* bq        = (const float*)d_in[9];
    const float* Wk        = (const float*)d_in[10];
    const float* bk        = (const float*)d_in[11];
    const float* Wv        = (const float*)d_in[12];
    const float* bv        = (const float*)d_in[13];
    const float* Wbias     = (const float*)d_in[14];
    const float* bbias     = (const float*)d_in[15];
    const float* Wo        = (const float*)d_in[16];
    const float* bo        = (const float*)d_in[17];
    const float* ln2_g     = (const float*)d_in[18];
    const float* ln2_b     = (const float*)d_in[19];
    const float* W1        = (const float*)d_in[20];
    const float* b1        = (const float*)d_in[21];
    const float* W2        = (const float*)d_in[22];
    const float* b2        = (const float*)d_in[23];
    const float* fln_g     = (const float*)d_in[24];
    const float* fln_b     = (const float*)d_in[25];
    const float* out_W     = (const float*)d_in[26];
    const float* out_b     = (const float*)d_in[27];

    float *h_, *y_, *sc_, *bqkv_;
    bf16 *yh_, *yl_, *qkvh_, *qkvl_, *oh_, *ol_, *fh_, *fl_;
    bf16 *ph_, *pl_, *vth_, *vtl_, *wh_, *wl_, *pb_;
    cudaGetSymbolAddress((void**)&h_,  g_h);
    cudaGetSymbolAddress((void**)&y_,  g_y);
    cudaGetSymbolAddress((void**)&sc_, g_sc);
    cudaGetSymbolAddress((void**)&bqkv_, g_bqkv);
    cudaGetSymbolAddress((void**)&yh_, g_yh);  cudaGetSymbolAddress((void**)&yl_, g_yl);
    cudaGetSymbolAddress((void**)&qkvh_, g_qkvh); cudaGetSymbolAddress((void**)&qkvl_, g_qkvl);
    cudaGetSymbolAddress((void**)&oh_, g_oh);  cudaGetSymbolAddress((void**)&ol_, g_ol);
    cudaGetSymbolAddress((void**)&fh_, g_fh);  cudaGetSymbolAddress((void**)&fl_, g_fl);
    cudaGetSymbolAddress((void**)&ph_, g_ph);  cudaGetSymbolAddress((void**)&pl_, g_pl);
    cudaGetSymbolAddress((void**)&vth_, g_vth); cudaGetSymbolAddress((void**)&vtl_, g_vtl);
    cudaGetSymbolAddress((void**)&wh_, g_wh);  cudaGetSymbolAddress((void**)&wl_, g_wl);
    cudaGetSymbolAddress((void**)&pb_, g_pb);

    cudaFuncSetAttribute(mma2<0,2,64>,  cudaFuncAttributeMaxDynamicSharedMemorySize, SMEM_MMA);
    cudaFuncSetAttribute(mma2<1,0,128>, cudaFuncAttributeMaxDynamicSharedMemorySize, SMEM_MMA);
    cudaFuncSetAttribute(mma2<2,0,128>, cudaFuncAttributeMaxDynamicSharedMemorySize, SMEM_MMA);
    cudaFuncSetAttribute(mma2<3,0,128>, cudaFuncAttributeMaxDynamicSharedMemorySize, SMEM_MMA);
    cudaFuncSetAttribute(mma2<4,1,128>, cudaFuncAttributeMaxDynamicSharedMemorySize, SMEM_MMA);

    // ---- weight pre-split (batched over layers; QKV fused into [2304][768]) ----
    const dim3 wb32(32, 8);
    wsplit_tr<<<dim3(HDIM/32, HDIM/32, NLAYER), wb32>>>(Wq, wh_, wl_, HDIM, HDIM, HH, 0);
    wsplit_tr<<<dim3(HDIM/32, HDIM/32, NLAYER), wb32>>>(Wk, wh_, wl_, HDIM, HDIM, HH, HH);
    wsplit_tr<<<dim3(HDIM/32, HDIM/32, NLAYER), wb32>>>(Wv, wh_, wl_, HDIM, HDIM, HH, 2*HH);
    wsplit_tr<<<dim3(HDIM/32, HDIM/32, NLAYER), wb32>>>(Wo, wh_, wl_, HDIM, HDIM, HH, 3*HH);
    wsplit_tr<<<dim3(FFND/32, HDIM/32, NLAYER), wb32>>>(W1, wh_, wl_, HDIM, FFND, HF, 4*HH);
    wsplit_tr<<<dim3(HDIM/32, FFND/32, NLAYER), wb32>>>(W2, wh_, wl_, FFND, HDIM, HF, 4*HH + HF);
    pack_bias<<<(NLAYER*QKVD + 255)/256, 256>>>(bq, bk, bv, bqkv_);

    encode_kernel<<<ROWS, 256>>>(x, enc_W, enc_b, gtok);

    const dim3 qkvgrid(QKVD/128, (ROWS + 127)/128);       // 18,57
    const dim3 ggrid(HDIM/128, (ROWS + 127)/128);         // 6,57
    const dim3 fgrid(FFND/128, (ROWS + 127)/128);         // 24,57
    const dim3 sgrid((SEQ+127)/128, (SEQ+127)/128, BATCH*NHEADS);  // 4,4,192
    const dim3 avgrid(1, (SEQ+127)/128, BATCH*NHEADS);
    const dim3 vtgrid((SEQ+31)/32, DKH/32, BATCH*NHEADS); // 15,2,192
    const int lnGrid = (ROWS + 7) / 8;
    const int smGrid = (BATCH*NHEADS*SEQ + 7) / 8;

    for (int i = 0; i < NLAYER; i++) {
        size_t off = (size_t)i * LSTR;
        bias_proj<<<dim3(SEQ, BATCH), 256>>>(attn_bias, Wbias + i*BDIM*NHEADS,
                                             bbias + i*NHEADS, gvd, pb_);
        ln_kernel<false><<<lnGrid, 256>>>(h_, ln1_g + i*HDIM, ln1_b + i*HDIM, yh_, yl_, nullptr);
        // fused QKV: N = 2304
        mma2<1,0,128><<<qkvgrid, 256, SMEM_MMA>>>(yh_, yl_, HDIM, wh_ + off, wl_ + off, HDIM,
            bqkv_ + i*QKVD, nullptr, qkvh_, qkvl_, nullptr, ROWS, QKVD, HDIM, QKVD, nullptr);
        vtrans_kernel<<<vtgrid, wb32>>>();
        mma2<4,1,128><<<sgrid, 256, SMEM_MMA>>>(qkvh_, qkvl_, QKVD, qkvh_, qkvl_, QKVD,
            nullptr, sc_, nullptr, nullptr, nullptr, SEQ, SEQ, DKH, SEQP, pb_);
        softmax_kernel<<<smGrid, 256>>>();
        mma2<0,2,64><<<avgrid, 256, SMEM_MMA>>>(ph_, pl_, PPITCH, vth_, vtl_, PPITCH,
            nullptr, nullptr, oh_, ol_, nullptr, SEQ, DKH, SEQ, HDIM, nullptr);
        mma2<3,0,128><<<ggrid, 256, SMEM_MMA>>>(oh_, ol_, HDIM, wh_ + off + 3*HH, wl_ + off + 3*HH, HDIM,
            bo + i*HDIM, h_, nullptr, nullptr, h_, ROWS, HDIM, HDIM, HDIM, nullptr);
        ln_kernel<false><<<lnGrid, 256>>>(h_, ln2_g + i*HDIM, ln2_b + i*HDIM, yh_, yl_, nullptr);
        mma2<2,0,128><<<fgrid, 256, SMEM_MMA>>>(yh_, yl_, HDIM, wh_ + off + 4*HH, wl_ + off + 4*HH, HDIM,
            b1 + i*FFND, nullptr, fh_, fl_, nullptr, ROWS, FFND, HDIM, FFND, nullptr);
        mma2<3,0,128><<<ggrid, 256, SMEM_MMA>>>(fh_, fl_, FFND, wh_ + off + 4*HH + HF, wl_ + off + 4*HH + HF, FFND,
            b2 + i*HDIM, h_, nullptr, nullptr, h_, ROWS, HDIM, FFND, HDIM, nullptr);
    }

    ln_kernel<true><<<lnGrid, 256>>>(h_, fln_g, fln_b, yh_, yl_, y_);
    readout_kernel<<<BATCH, 256>>>(out_W, out_b, (float*)d_out);
}

// round 8
// speedup vs baseline: 4.1105x; 1.1094x over previous
#include <cuda_runtime.h>
#include <cuda_bf16.h>
#include <math.h>
#include <stdint.h>
#include <string.h>

#define BATCH   16
#define NNODES  448
#define SEQ     449
#define PPITCH  456            /* bf16 vt row pitch */
#define PBP     456            /* bias-projection row pitch */
#define HDIM    768
#define QKVD    (3*HDIM)       /* 2304 */
#define NHEADS  12
#define DKH     64
#define FFND    3072
#define BDIM    8
#define NLAYER  6
#define OUTD    10
#define INDIM   128
#define EPSV    1e-5f
#define SCALEV  0.125f
#define ROWS    (BATCH*SEQ)   /* 7184 */

#define HH      ((size_t)HDIM*HDIM)
#define HF      ((size_t)HDIM*FFND)
#define LSTR    (4*HH + 2*HF)
#define SMEM_MMA 81920
/* fa smem: Q 128x72x2B x2 = 36864 ; 2 KV bufs x (K+V hi/lo) = 2x36864 */
#define SMEM_FA  110592

typedef __nv_bfloat16 bf16;

// ---------------- scratch (device globals: alloc-free) ----------------
__device__ float g_h [(size_t)ROWS*HDIM];
__device__ float g_y [(size_t)ROWS*HDIM];
__device__ float g_bqkv[(size_t)NLAYER*QKVD];

__device__ __align__(16) bf16 g_yh[(size_t)ROWS*HDIM];
__device__ __align__(16) bf16 g_yl[(size_t)ROWS*HDIM];
__device__ __align__(16) bf16 g_qkvh[(size_t)ROWS*QKVD];
__device__ __align__(16) bf16 g_qkvl[(size_t)ROWS*QKVD];
__device__ __align__(16) bf16 g_oh[(size_t)ROWS*HDIM];
__device__ __align__(16) bf16 g_ol[(size_t)ROWS*HDIM];
__device__ __align__(16) bf16 g_fh[(size_t)ROWS*FFND];
__device__ __align__(16) bf16 g_fl[(size_t)ROWS*FFND];
__device__ __align__(16) bf16 g_vth[(size_t)BATCH*NHEADS*DKH*PPITCH + 64];
__device__ __align__(16) bf16 g_vtl[(size_t)BATCH*NHEADS*DKH*PPITCH + 64];
__device__ __align__(16) bf16 g_wh[(size_t)NLAYER*LSTR];
__device__ __align__(16) bf16 g_wl[(size_t)NLAYER*LSTR];
__device__ __align__(16) bf16 g_pb[(size_t)BATCH*NHEADS*SEQ*PBP];

// ---------------- helpers ----------------
__device__ __forceinline__ uint32_t smem_u32(const void* p) {
    uint32_t a;
    asm("{ .reg .u64 t; cvta.to.shared.u64 t, %1; cvt.u32.u64 %0, t; }" : "=r"(a) : "l"(p));
    return a;
}
__device__ __forceinline__ uint32_t packbf(bf16 a, bf16 b) {
    __nv_bfloat162 t; t.x = a; t.y = b;
    uint32_t u; memcpy(&u, &t, 4); return u;
}
__device__ __forceinline__ uint32_t packf2(float a, float b) {
    return packbf(__float2bfloat16(a), __float2bfloat16(b));
}
__device__ __forceinline__ uint32_t packf2lo(float a, float b) {
    bf16 ha = __float2bfloat16(a), hb = __float2bfloat16(b);
    return packbf(__float2bfloat16(a - __bfloat162float(ha)),
                  __float2bfloat16(b - __bfloat162float(hb)));
}
__device__ __forceinline__ void split_pair(float v0, float v1, bf16* H, bf16* L, size_t idx) {
    bf16 h0 = __float2bfloat16(v0), h1 = __float2bfloat16(v1);
    bf16 l0 = __float2bfloat16(v0 - __bfloat162float(h0));
    bf16 l1 = __float2bfloat16(v1 - __bfloat162float(h1));
    *(uint32_t*)(H + idx) = packbf(h0, h1);
    *(uint32_t*)(L + idx) = packbf(l0, l1);
}
__device__ __forceinline__ void cpa(uint32_t dst, const bf16* src, int bytes) {
    asm volatile("cp.async.cg.shared.global [%0], [%1], 16, %2;"
                 :: "r"(dst), "l"(__cvta_generic_to_global(src)), "r"(bytes));
}
#define CP_COMMIT() asm volatile("cp.async.commit_group;" ::: "memory")
#define CP_WAIT0()  asm volatile("cp.async.wait_group 0;" ::: "memory")
#define CP_WAIT1()  asm volatile("cp.async.wait_group 1;" ::: "memory")

#define LDMX4(r0,r1,r2,r3,addr) \
    asm volatile("ldmatrix.sync.aligned.m8n8.x4.shared.b16 {%0,%1,%2,%3}, [%4];" \
        : "=r"(r0),"=r"(r1),"=r"(r2),"=r"(r3) : "r"(addr))

#define MMA16816(c,a,b) \
    asm volatile("mma.sync.aligned.m16n8k16.row.col.f32.bf16.bf16.f32 " \
        "{%0,%1,%2,%3},{%4,%5,%6,%7},{%8,%9},{%0,%1,%2,%3};" \
        : "+f"((c)[0]),"+f"((c)[1]),"+f"((c)[2]),"+f"((c)[3]) \
        : "r"((a)[0]),"r"((a)[1]),"r"((a)[2]),"r"((a)[3]),"r"((b)[0]),"r"((b)[1]))

__device__ __forceinline__ float wred_sum(float v) {
    #pragma unroll
    for (int o = 16; o > 0; o >>= 1) v += __shfl_xor_sync(0xffffffffu, v, o);
    return v;
}
__device__ __forceinline__ float wred_max(float v) {
    #pragma unroll
    for (int o = 16; o > 0; o >>= 1) v = fmaxf(v, __shfl_xor_sync(0xffffffffu, v, o));
    return v;
}

// ============== bf16x3 MMA GEMM (weight GEMMs) ==============
// EPI: 1 bias+split out (QKV), 2 bias+gelu+split (FFN1), 3 bias+res fp32 (Wo/FFN2)
template<int EPI>
__global__ void __launch_bounds__(256, 2)
mma2(const bf16* __restrict__ Ah, const bf16* __restrict__ Al, int lda,
     const bf16* __restrict__ Bh, const bf16* __restrict__ Bl, int ldb,
     const float* __restrict__ bias,
     float* __restrict__ Cf, bf16* __restrict__ Ch, bf16* __restrict__ Cl,
     const float* __restrict__ Res,
     int M, int N, int K, int ldc) {
    extern __shared__ __align__(16) char smem[];
    const int tid = threadIdx.x, wid = tid >> 5, lane = tid & 31;
    const int mbase = blockIdx.y * 128, nbase = blockIdx.x * 128;

    const uint32_t sbase = smem_u32(smem);
    float acc[2][8][4];
    #pragma unroll
    for (int i = 0; i < 2; i++)
        #pragma unroll
        for (int j = 0; j < 8; j++)
            #pragma unroll
            for (int e = 0; e < 4; e++) acc[i][j][e] = 0.f;

    const int wm = (wid & 3) * 32, wn = (wid >> 2) * 64;
    const int nkc = (K + 31) >> 5;

    auto stage = [&](int buf, int kc) {
        uint32_t sb0 = sbase + buf * 40960;
        #pragma unroll
        for (int m = 0; m < 2; m++) {
            int c = tid + m * 256;
            int row = c >> 2, k8 = c & 3;
            int kpos = kc + k8 * 8;
            int kb = K - kpos;
            int kbytes = kb <= 0 ? 0 : (kb >= 8 ? 16 : kb * 2);
            int kposc = kb <= 0 ? 0 : kpos;
            uint32_t doff = (uint32_t)row * 80u + (uint32_t)k8 * 16u;
            {
                int gr = mbase + row;
                int ok = (gr < M) ? kbytes : 0;
                int grc = (gr < M) ? gr : 0;
                size_t gi = (size_t)grc * lda + kposc;
                cpa(sb0 + doff, Ah + gi, ok);
                cpa(sb0 + 10240 + doff, Al + gi, ok);
            }
            {
                int gn = nbase + row;
                int ok = (gn < N) ? kbytes : 0;
                int gnc = (gn < N) ? gn : 0;
                size_t gi = (size_t)gnc * ldb + kposc;
                cpa(sb0 + 20480 + doff, Bh + gi, ok);
                cpa(sb0 + 30720 + doff, Bl + gi, ok);
            }
        }
        CP_COMMIT();
    };

    stage(0, 0);
    for (int ic = 0; ic < nkc; ic++) {
        int buf = ic & 1;
        if (ic + 1 < nkc) { stage(buf ^ 1, (ic + 1) * 32); CP_WAIT1(); }
        else              { CP_WAIT0(); }
        __syncthreads();

        const uint32_t aHb = sbase + buf * 40960, aLb = aHb + 10240;
        const uint32_t bHb = aHb + 20480, bLb = aHb + 30720;
        #pragma unroll
        for (int ks = 0; ks < 2; ks++) {
            uint32_t bh[8][2], bl[8][2];
            int bn = ((lane >> 4) << 3) + (lane & 7);
            int bkh = (lane >> 3) & 1;
            #pragma unroll
            for (int g = 0; g < 4; g++) {
                uint32_t off = (uint32_t)(wn + g * 16 + bn) * 80u + (uint32_t)(ks * 16 + bkh * 8) * 2u;
                LDMX4(bh[2*g][0], bh[2*g][1], bh[2*g+1][0], bh[2*g+1][1], bHb + off);
                LDMX4(bl[2*g][0], bl[2*g][1], bl[2*g+1][0], bl[2*g+1][1], bLb + off);
            }
            #pragma unroll
            for (int i = 0; i < 2; i++) {
                int ar = wm + i * 16 + (lane & 15);
                uint32_t off = (uint32_t)ar * 80u + (uint32_t)(ks * 16 + (lane >> 4) * 8) * 2u;
                uint32_t ah[4], al[4];
                LDMX4(ah[0], ah[1], ah[2], ah[3], aHb + off);
                LDMX4(al[0], al[1], al[2], al[3], aLb + off);
                #pragma unroll
                for (int j = 0; j < 8; j++) {
                    MMA16816(acc[i][j], ah, bh[j]);
                    MMA16816(acc[i][j], ah, bl[j]);
                    MMA16816(acc[i][j], al, bh[j]);
                }
            }
        }
        __syncthreads();
    }

    // ---- epilogue ----
    #pragma unroll
    for (int i = 0; i < 2; i++) {
        #pragma unroll
        for (int hf = 0; hf < 2; hf++) {
            int row = mbase + wm + i * 16 + (lane >> 2) + hf * 8;
            if (row >= M) continue;
            #pragma unroll
            for (int j = 0; j < 8; j++) {
                int col = nbase + wn + j * 8 + (lane & 3) * 2;
                if (col >= N) continue;
                float c0 = acc[i][j][hf * 2 + 0];
                float c1 = acc[i][j][hf * 2 + 1];
                if (EPI == 1) {
                    split_pair(c0 + bias[col], c1 + bias[col + 1], Ch, Cl,
                               (size_t)row * ldc + col);
                } else if (EPI == 2) {
                    float t0 = c0 + bias[col], t1 = c1 + bias[col + 1];
                    t0 = 0.5f * t0 * (1.f + erff(t0 * 0.70710678118654752f));
                    t1 = 0.5f * t1 * (1.f + erff(t1 * 0.70710678118654752f));
                    split_pair(t0, t1, Ch, Cl, (size_t)row * ldc + col);
                } else {
                    size_t idx = (size_t)row * ldc + col;
                    Cf[idx]     = c0 + bias[col]     + Res[idx];
                    Cf[idx + 1] = c1 + bias[col + 1] + Res[idx + 1];
                }
            }
        }
    }
}

// ============== fused flash attention ==============
// grid (ceil(SEQ/128), B*NHEADS), 256 threads (8 warps x 16 q-rows)
// Q,K from g_qkv (hi/lo), V^T from g_vt (hi/lo), bias from g_pb; writes g_oh/g_ol.
__global__ void __launch_bounds__(256, 2)
fa_kernel() {
    extern __shared__ __align__(16) char smem[];
    const int tid = threadIdx.x, wid = tid >> 5, lane = tid & 31;
    const int q0 = blockIdx.x * 128;
    const int z = blockIdx.y;
    const int b = z / NHEADS, h = z - b * NHEADS;
    const uint32_t sb = smem_u32(smem);
    const uint32_t sQh = sb, sQl = sb + 18432;
    const size_t qbase = (size_t)b * SEQ * QKVD + h * DKH;

    // ---- stage Q tile (once) ----
    #pragma unroll
    for (int it = 0; it < 4; it++) {
        int c = tid + it * 256;
        int row = c >> 3, k8 = c & 7;
        int q = q0 + row;
        int ok = (q < SEQ) ? 16 : 0;
        int qc = (q < SEQ) ? q : 0;
        size_t gi = qbase + (size_t)qc * QKVD + k8 * 8;
        uint32_t doff = (uint32_t)row * 144u + (uint32_t)k8 * 16u;
        cpa(sQh + doff, g_qkvh + gi, ok);
        cpa(sQl + doff, g_qkvl + gi, ok);
    }
    CP_COMMIT();

    auto stageKV = [&](int buf, int kt) {
        uint32_t sK = sb + 36864 + buf * 36864;
        int k0 = kt * 64;
        #pragma unroll
        for (int it = 0; it < 2; it++) {
            int c = tid + it * 256;
            int row = c >> 3, k8 = c & 7;
            uint32_t doff = (uint32_t)row * 144u + (uint32_t)k8 * 16u;
            {   // K rows (seq)
                int s = k0 + row;
                int ok = (s < SEQ) ? 16 : 0;
                int sc = (s < SEQ) ? s : 0;
                size_t gi = qbase + HDIM + (size_t)sc * QKVD + k8 * 8;
                cpa(sK + doff, g_qkvh + gi, ok);
                cpa(sK + 9216 + doff, g_qkvl + gi, ok);
            }
            {   // V^T rows (d), cols seq
                int kpos = k0 + k8 * 8;
                int ok = (kpos + 8 <= PPITCH) ? 16 : (kpos < PPITCH ? (PPITCH - kpos) * 2 : 0);
                int kc = (kpos < PPITCH) ? kpos : 0;
                size_t gi = (size_t)z * DKH * PPITCH + (size_t)row * PPITCH + kc;
                cpa(sK + 18432 + doff, g_vth + gi, ok);
                cpa(sK + 27648 + doff, g_vtl + gi, ok);
            }
        }
        CP_COMMIT();
    };
    stageKV(0, 0);

    float oacc[8][4];
    #pragma unroll
    for (int j = 0; j < 8; j++)
        #pragma unroll
        for (int e = 0; e < 4; e++) oacc[j][e] = 0.f;
    float mrow0 = -1e30f, mrow1 = -1e30f, lrow0 = 0.f, lrow1 = 0.f;

    const int wm = wid * 16;
    const int r0 = lane >> 2;
    const int qr0 = q0 + wm + r0, qr1 = qr0 + 8;
    const bf16* pb0 = g_pb + ((size_t)z * SEQ + (qr0 < SEQ ? qr0 : SEQ - 1)) * PBP;
    const bf16* pb1 = g_pb + ((size_t)z * SEQ + (qr1 < SEQ ? qr1 : SEQ - 1)) * PBP;
    const int NT = (SEQ + 63) / 64;   // 8

    for (int kt = 0; kt < NT; kt++) {
        int buf = kt & 1;
        if (kt + 1 < NT) { stageKV(buf ^ 1, kt + 1); CP_WAIT1(); }
        else             { CP_WAIT0(); }
        __syncthreads();
        uint32_t sK = sb + 36864 + buf * 36864;
        uint32_t sKh = sK, sKl = sK + 9216, sVh = sK + 18432, sVl = sK + 27648;

        // ---- S = Q K^T (bf16x3) ----
        float sacc[8][4];
        #pragma unroll
        for (int j = 0; j < 8; j++)
            #pragma unroll
            for (int e = 0; e < 4; e++) sacc[j][e] = 0.f;
        int bn = ((lane >> 4) << 3) + (lane & 7);
        int bkh = (lane >> 3) & 1;
        #pragma unroll
        for (int ks = 0; ks < 4; ks++) {
            uint32_t bh[8][2], bl[8][2];
            #pragma unroll
            for (int g = 0; g < 4; g++) {
                uint32_t off = (uint32_t)(g * 16 + bn) * 144u + (uint32_t)(ks * 16 + bkh * 8) * 2u;
                LDMX4(bh[2*g][0], bh[2*g][1], bh[2*g+1][0], bh[2*g+1][1], sKh + off);
                LDMX4(bl[2*g][0], bl[2*g][1], bl[2*g+1][0], bl[2*g+1][1], sKl + off);
            }
            uint32_t ah[4], al[4];
            uint32_t aoff = (uint32_t)(wm + (lane & 15)) * 144u + (uint32_t)(ks * 16 + (lane >> 4) * 8) * 2u;
            LDMX4(ah[0], ah[1], ah[2], ah[3], sQh + aoff);
            LDMX4(al[0], al[1], al[2], al[3], sQl + aoff);
            #pragma unroll
            for (int j = 0; j < 8; j++) {
                MMA16816(sacc[j], ah, bh[j]);
                MMA16816(sacc[j], ah, bl[j]);
                MMA16816(sacc[j], al, bh[j]);
            }
        }

        // ---- scale + bias + mask ----
        int k0 = kt * 64;
        #pragma unroll
        for (int j = 0; j < 8; j++) {
            int jc = j * 8 + (lane & 3) * 2;
            int kc = k0 + jc;
            float b00 = (kc     < SEQ) ? __bfloat162float(pb0[kc])     : -1e30f;
            float b01 = (kc + 1 < SEQ) ? __bfloat162float(pb0[kc + 1]) : -1e30f;
            float b10 = (kc     < SEQ) ? __bfloat162float(pb1[kc])     : -1e30f;
            float b11 = (kc + 1 < SEQ) ? __bfloat162float(pb1[kc + 1]) : -1e30f;
            sacc[j][0] = sacc[j][0] * SCALEV + b00;
            sacc[j][1] = sacc[j][1] * SCALEV + b01;
            sacc[j][2] = sacc[j][2] * SCALEV + b10;
            sacc[j][3] = sacc[j][3] * SCALEV + b11;
        }

        // ---- online softmax ----
        float t0 = -1e30f, t1 = -1e30f;
        #pragma unroll
        for (int j = 0; j < 8; j++) {
            t0 = fmaxf(t0, fmaxf(sacc[j][0], sacc[j][1]));
            t1 = fmaxf(t1, fmaxf(sacc[j][2], sacc[j][3]));
        }
        t0 = fmaxf(t0, __shfl_xor_sync(0xffffffffu, t0, 1));
        t0 = fmaxf(t0, __shfl_xor_sync(0xffffffffu, t0, 2));
        t1 = fmaxf(t1, __shfl_xor_sync(0xffffffffu, t1, 1));
        t1 = fmaxf(t1, __shfl_xor_sync(0xffffffffu, t1, 2));
        float m0n = fmaxf(mrow0, t0), m1n = fmaxf(mrow1, t1);
        float sc0 = __expf(mrow0 - m0n), sc1 = __expf(mrow1 - m1n);
        mrow0 = m0n; mrow1 = m1n;
        float s0 = 0.f, s1 = 0.f;
        #pragma unroll
        for (int j = 0; j < 8; j++) {
            sacc[j][0] = __expf(sacc[j][0] - m0n);
            sacc[j][1] = __expf(sacc[j][1] - m0n);
            sacc[j][2] = __expf(sacc[j][2] - m1n);
            sacc[j][3] = __expf(sacc[j][3] - m1n);
            s0 += sacc[j][0] + sacc[j][1];
            s1 += sacc[j][2] + sacc[j][3];
        }
        s0 += __shfl_xor_sync(0xffffffffu, s0, 1);
        s0 += __shfl_xor_sync(0xffffffffu, s0, 2);
        s1 += __shfl_xor_sync(0xffffffffu, s1, 1);
        s1 += __shfl_xor_sync(0xffffffffu, s1, 2);
        lrow0 = lrow0 * sc0 + s0;
        lrow1 = lrow1 * sc1 + s1;
        #pragma unroll
        for (int j = 0; j < 8; j++) {
            oacc[j][0] *= sc0; oacc[j][1] *= sc0;
            oacc[j][2] *= sc1; oacc[j][3] *= sc1;
        }

        // ---- O += P V^T (bf16x3, P from registers) ----
        #pragma unroll
        for (int ks = 0; ks < 4; ks++) {
            uint32_t ah[4], al[4];
            ah[0] = packf2(sacc[2*ks][0],   sacc[2*ks][1]);
            ah[1] = packf2(sacc[2*ks][2],   sacc[2*ks][3]);
            ah[2] = packf2(sacc[2*ks+1][0], sacc[2*ks+1][1]);
            ah[3] = packf2(sacc[2*ks+1][2], sacc[2*ks+1][3]);
            al[0] = packf2lo(sacc[2*ks][0],   sacc[2*ks][1]);
            al[1] = packf2lo(sacc[2*ks][2],   sacc[2*ks][3]);
            al[2] = packf2lo(sacc[2*ks+1][0], sacc[2*ks+1][1]);
            al[3] = packf2lo(sacc[2*ks+1][2], sacc[2*ks+1][3]);
            uint32_t bh[8][2], bl[8][2];
            #pragma unroll
            for (int g = 0; g < 4; g++) {
                uint32_t off = (uint32_t)(g * 16 + bn) * 144u + (uint32_t)(ks * 16 + bkh * 8) * 2u;
                LDMX4(bh[2*g][0], bh[2*g][1], bh[2*g+1][0], bh[2*g+1][1], sVh + off);
                LDMX4(bl[2*g][0], bl[2*g][1], bl[2*g+1][0], bl[2*g+1][1], sVl + off);
            }
            #pragma unroll
            for (int j = 0; j < 8; j++) {
                MMA16816(oacc[j], ah, bh[j]);
                MMA16816(oacc[j], ah, bl[j]);
                MMA16816(oacc[j], al, bh[j]);
            }
        }
        __syncthreads();
    }

    // ---- store O / l ----
    float inv0 = 1.f / lrow0, inv1 = 1.f / lrow1;
    #pragma unroll
    for (int j = 0; j < 8; j++) {
        int col = h * DKH + j * 8 + (lane & 3) * 2;
        if (qr0 < SEQ)
            split_pair(oacc[j][0] * inv0, oacc[j][1] * inv0, g_oh, g_ol,
                       (size_t)(b * SEQ + qr0) * HDIM + col);
        if (qr1 < SEQ)
            split_pair(oacc[j][2] * inv1, oacc[j][3] * inv1, g_oh, g_ol,
                       (size_t)(b * SEQ + qr1) * HDIM + col);
    }
}

// ---------------- per-layer bias projection ----------------
__global__ void bias_proj(const float* __restrict__ ab, const float* __restrict__ Wb,
                          const float* __restrict__ bb, const float* __restrict__ gvd,
                          bf16* __restrict__ pb) {
    int q = blockIdx.x, b = blockIdx.y;
    int tid = threadIdx.x;
    __shared__ float w[BDIM][NHEADS];
    __shared__ float vv[NHEADS];
    if (tid < BDIM * NHEADS) w[tid / NHEADS][tid % NHEADS] = Wb[tid];
    __syncthreads();
    if (tid < NHEADS) {
        float s = bb[tid];
        #pragma unroll
        for (int d = 0; d < BDIM; d++) s += gvd[d] * w[d][tid];
        vv[tid] = s;
    }
    __syncthreads();
    bool qv = (q >= NNODES);
    for (int k = tid; k < SEQ; k += 256) {
        bool virt = qv || (k >= NNODES);
        float f[8];
        if (!virt) {
            const float* p = ab + (((size_t)b * NNODES + q) * NNODES + k) * BDIM;
            float4 x0 = *(const float4*)p;
            float4 x1 = *(const float4*)(p + 4);
            f[0]=x0.x; f[1]=x0.y; f[2]=x0.z; f[3]=x0.w;
            f[4]=x1.x; f[5]=x1.y; f[6]=x1.z; f[7]=x1.w;
        }
        #pragma unroll
        for (int h = 0; h < NHEADS; h++) {
            float val;
            if (virt) val = vv[h];
            else {
                val = bb[h];
                #pragma unroll
                for (int d = 0; d < BDIM; d++) val += f[d] * w[d][h];
            }
            pb[(((size_t)(b * NHEADS + h)) * SEQ + q) * PBP + k] = __float2bfloat16(val);
        }
    }
}

// ---------------- weight transpose + split, batched over layers ----------------
__global__ void wsplit_tr(const float* __restrict__ W, bf16* __restrict__ oh,
                          bf16* __restrict__ ol, int K, int N,
                          size_t sin, size_t obase) {
    __shared__ float t[32][33];
    int k0 = blockIdx.y * 32, n0 = blockIdx.x * 32;
    size_t iz = (size_t)blockIdx.z * sin;
    size_t oz = (size_t)blockIdx.z * LSTR + obase;
    int tx = threadIdx.x, ty = threadIdx.y;
    #pragma unroll
    for (int j = 0; j < 32; j += 8)
        t[ty + j][tx] = W[iz + (size_t)(k0 + ty + j) * N + n0 + tx];
    __syncthreads();
    #pragma unroll
    for (int j = 0; j < 32; j += 8) {
        float v = t[tx][ty + j];
        size_t o = oz + (size_t)(n0 + ty + j) * K + k0 + tx;
        bf16 h = __float2bfloat16(v);
        oh[o] = h;
        ol[o] = __float2bfloat16(v - __bfloat162float(h));
    }
}

// ---------------- pack QKV bias ----------------
__global__ void pack_bias(const float* __restrict__ bq, const float* __restrict__ bk,
                          const float* __restrict__ bv, float* __restrict__ o) {
    int i = blockIdx.x * 256 + threadIdx.x;
    int z = i / QKVD, c = i % QKVD;
    if (z >= NLAYER) return;
    float v;
    if (c < HDIM)            v = bq[z * HDIM + c];
    else if (c < 2 * HDIM)   v = bk[z * HDIM + c - HDIM];
    else                     v = bv[z * HDIM + c - 2 * HDIM];
    o[i] = v;
}

// ---------------- V transpose (from combined qkv buffer) ----------------
__global__ void vtrans_kernel() {
    int z = blockIdx.z, b = z / NHEADS, h = z - b * NHEADS;
    int s0 = blockIdx.x * 32, d0 = blockIdx.y * 32;
    __shared__ bf16 th[32][33], tl[32][33];
    int tx = threadIdx.x, ty = threadIdx.y;
    #pragma unroll
    for (int j = 0; j < 32; j += 8) {
        int s = s0 + ty + j;
        bf16 vh = __float2bfloat16(0.f), vl = vh;
        if (s < SEQ) {
            size_t idx = (size_t)(b * SEQ + s) * QKVD + 2 * HDIM + h * DKH + d0 + tx;
            vh = g_qkvh[idx]; vl = g_qkvl[idx];
        }
        th[ty + j][tx] = vh; tl[ty + j][tx] = vl;
    }
    __syncthreads();
    #pragma unroll
    for (int j = 0; j < 32; j += 8) {
        int d = d0 + ty + j, s = s0 + tx;
        if (s < PPITCH) {
            size_t o = ((size_t)z * DKH + d) * PPITCH + s;
            g_vth[o] = th[tx][ty + j];
            g_vtl[o] = tl[tx][ty + j];
        }
    }
}

// ---------------- node encoder + graph token ----------------
__global__ void encode_kernel(const float* __restrict__ x, const float* __restrict__ W,
                              const float* __restrict__ b, const float* __restrict__ gt) {
    int r = blockIdx.x;
    int bb = r / SEQ, s = r % SEQ;
    int tid = threadIdx.x;
    if (s == NNODES) {
        for (int c = tid; c < HDIM; c += 256) g_h[(size_t)r*HDIM + c] = gt[c];
        return;
    }
    __shared__ float xs[INDIM];
    const float* xr = x + ((size_t)bb*NNODES + s)*INDIM;
    if (tid < INDIM) xs[tid] = xr[tid];
    __syncthreads();
    for (int c = tid; c < HDIM; c += 256) {
        float acc = b[c];
        #pragma unroll 8
        for (int k = 0; k < INDIM; k++) acc += xs[k]*W[k*HDIM + c];
        g_h[(size_t)r*HDIM + c] = acc;
    }
}

// ---------------- layernorm: warp-per-row ----------------
template<bool F32OUT>
__global__ void ln_kernel(const float* __restrict__ in, const float* __restrict__ g,
                          const float* __restrict__ bta, bf16* __restrict__ oh,
                          bf16* __restrict__ ol, float* __restrict__ of) {
    int wid = threadIdx.x >> 5, lane = threadIdx.x & 31;
    int r = blockIdx.x * 8 + wid;
    if (r >= ROWS) return;
    const float4* row = (const float4*)(in + (size_t)r * HDIM);
    const float4* g4 = (const float4*)g;
    const float4* b4 = (const float4*)bta;
    float4 v[6];
    float s = 0.f;
    #pragma unroll
    for (int i = 0; i < 6; i++) {
        v[i] = row[lane + i * 32];
        s += v[i].x + v[i].y + v[i].z + v[i].w;
    }
    s = wred_sum(s);
    float mean = s * (1.f / HDIM);
    float vs = 0.f;
    #pragma unroll
    for (int i = 0; i < 6; i++) {
        float d0 = v[i].x - mean, d1 = v[i].y - mean, d2 = v[i].z - mean, d3 = v[i].w - mean;
        vs += d0*d0 + d1*d1 + d2*d2 + d3*d3;
    }
    vs = wred_sum(vs);
    float rstd = rsqrtf(vs * (1.f / HDIM) + EPSV);
    #pragma unroll
    for (int i = 0; i < 6; i++) {
        int c4 = lane + i * 32;
        float4 gg = g4[c4], bb = b4[c4];
        float o0 = (v[i].x - mean) * rstd * gg.x + bb.x;
        float o1 = (v[i].y - mean) * rstd * gg.y + bb.y;
        float o2 = (v[i].z - mean) * rstd * gg.z + bb.z;
        float o3 = (v[i].w - mean) * rstd * gg.w + bb.w;
        size_t idx = (size_t)r * HDIM + c4 * 4;
        split_pair(o0, o1, oh, ol, idx);
        split_pair(o2, o3, oh, ol, idx + 2);
        if (F32OUT) *(float4*)(of + idx) = make_float4(o0, o1, o2, o3);
    }
}

// ---------------- readout ----------------
__global__ void readout_kernel(const float* __restrict__ W, const float* __restrict__ bo,
                               float* __restrict__ out) {
    int b = blockIdx.x;
    int tid = threadIdx.x;
    const float* y = g_y + (size_t)(b*SEQ)*HDIM;
    __shared__ float red[256];
    __shared__ float logits[OUTD];
    float acc[OUTD];
    #pragma unroll
    for (int o = 0; o < OUTD; o++) acc[o] = 0.f;
    for (int k = tid; k < HDIM; k += 256) {
        float yv = y[k];
        #pragma unroll
        for (int o = 0; o < OUTD; o++) acc[o] += yv*W[k*OUTD + o];
    }
    for (int o = 0; o < OUTD; o++) {
        red[tid] = acc[o]; __syncthreads();
        for (int s = 128; s > 0; s >>= 1) { if (tid < s) red[tid] += red[tid+s]; __syncthreads(); }
        if (tid == 0) logits[o] = red[0] + bo[o];
        __syncthreads();
    }
    if (tid == 0) {
        float m = -1e30f;
        for (int o = 0; o < OUTD; o++) m = fmaxf(m, logits[o]);
        float s = 0.f;
        for (int o = 0; o < OUTD; o++) s += expf(logits[o]-m);
        float lse = m + logf(s);
        for (int o = 0; o < OUTD; o++) out[b*OUTD + o] = logits[o] - lse;
    }
}

extern "C" void kernel_launch(void* const* d_in, const int* in_sizes, int n_in,
                              void* d_out, int out_size) {
    const float* attn_bias = (const float*)d_in[0];
    const float* x         = (const float*)d_in[1];
    const float* enc_W     = (const float*)d_in[2];
    const float* enc_b     = (const float*)d_in[3];
    const float* gtok      = (const float*)d_in[4];
    const float* gvd       = (const float*)d_in[5];
    const float* ln1_g     = (const float*)d_in[6];
    const float* ln1_b     = (const float*)d_in[7];
    const float* Wq        = (const float*)d_in[8];
    const float* bq        = (const float*)d_in[9];
    const float* Wk        = (const float*)d_in[10];
    const float* bk        = (const float*)d_in[11];
    const float* Wv        = (const float*)d_in[12];
    const float* bv        = (const float*)d_in[13];
    const float* Wbias     = (const float*)d_in[14];
    const float* bbias     = (const float*)d_in[15];
    const float* Wo        = (const float*)d_in[16];
    const float* bo        = (const float*)d_in[17];
    const float* ln2_g     = (const float*)d_in[18];
    const float* ln2_b     = (const float*)d_in[19];
    const float* W1        = (const float*)d_in[20];
    const float* b1        = (const float*)d_in[21];
    const float* W2        = (const float*)d_in[22];
    const float* b2        = (const float*)d_in[23];
    const float* fln_g     = (const float*)d_in[24];
    const float* fln_b     = (const float*)d_in[25];
    const float* out_W     = (const float*)d_in[26];
    const float* out_b     = (const float*)d_in[27];

    float *h_, *y_, *bqkv_;
    bf16 *yh_, *yl_, *qkvh_, *qkvl_, *oh_, *ol_, *fh_, *fl_, *wh_, *wl_, *pb_;
    cudaGetSymbolAddress((void**)&h_,  g_h);
    cudaGetSymbolAddress((void**)&y_,  g_y);
    cudaGetSymbolAddress((void**)&bqkv_, g_bqkv);
    cudaGetSymbolAddress((void**)&yh_, g_yh);  cudaGetSymbolAddress((void**)&yl_, g_yl);
    cudaGetSymbolAddress((void**)&qkvh_, g_qkvh); cudaGetSymbolAddress((void**)&qkvl_, g_qkvl);
    cudaGetSymbolAddress((void**)&oh_, g_oh);  cudaGetSymbolAddress((void**)&ol_, g_ol);
    cudaGetSymbolAddress((void**)&fh_, g_fh);  cudaGetSymbolAddress((void**)&fl_, g_fl);
    cudaGetSymbolAddress((void**)&wh_, g_wh);  cudaGetSymbolAddress((void**)&wl_, g_wl);
    cudaGetSymbolAddress((void**)&pb_, g_pb);

    cudaFuncSetAttribute(mma2<1>, cudaFuncAttributeMaxDynamicSharedMemorySize, SMEM_MMA);
    cudaFuncSetAttribute(mma2<2>, cudaFuncAttributeMaxDynamicSharedMemorySize, SMEM_MMA);
    cudaFuncSetAttribute(mma2<3>, cudaFuncAttributeMaxDynamicSharedMemorySize, SMEM_MMA);
    cudaFuncSetAttribute(fa_kernel, cudaFuncAttributeMaxDynamicSharedMemorySize, SMEM_FA);

    // ---- weight pre-split (batched over layers; QKV fused into [2304][768]) ----
    const dim3 wb32(32, 8);
    wsplit_tr<<<dim3(HDIM/32, HDIM/32, NLAYER), wb32>>>(Wq, wh_, wl_, HDIM, HDIM, HH, 0);
    wsplit_tr<<<dim3(HDIM/32, HDIM/32, NLAYER), wb32>>>(Wk, wh_, wl_, HDIM, HDIM, HH, HH);
    wsplit_tr<<<dim3(HDIM/32, HDIM/32, NLAYER), wb32>>>(Wv, wh_, wl_, HDIM, HDIM, HH, 2*HH);
    wsplit_tr<<<dim3(HDIM/32, HDIM/32, NLAYER), wb32>>>(Wo, wh_, wl_, HDIM, HDIM, HH, 3*HH);
    wsplit_tr<<<dim3(FFND/32, HDIM/32, NLAYER), wb32>>>(W1, wh_, wl_, HDIM, FFND, HF, 4*HH);
    wsplit_tr<<<dim3(HDIM/32, FFND/32, NLAYER), wb32>>>(W2, wh_, wl_, FFND, HDIM, HF, 4*HH + HF);
    pack_bias<<<(NLAYER*QKVD + 255)/256, 256>>>(bq, bk, bv, bqkv_);

    encode_kernel<<<ROWS, 256>>>(x, enc_W, enc_b, gtok);

    const dim3 qkvgrid(QKVD/128, (ROWS + 127)/128);       // 18,57
    const dim3 ggrid(HDIM/128, (ROWS + 127)/128);         // 6,57
    const dim3 fgrid(FFND/128, (ROWS + 127)/128);         // 24,57
    const dim3 fagrid((SEQ + 127)/128, BATCH*NHEADS);     // 4,192
    const dim3 vtgrid((SEQ+31)/32, DKH/32, BATCH*NHEADS); // 15,2,192
    const int lnGrid = (ROWS + 7) / 8;

    for (int i = 0; i < NLAYER; i++) {
        size_t off = (size_t)i * LSTR;
        bias_proj<<<dim3(SEQ, BATCH), 256>>>(attn_bias, Wbias + i*BDIM*NHEADS,
                                             bbias + i*NHEADS, gvd, pb_);
        ln_kernel<false><<<lnGrid, 256>>>(h_, ln1_g + i*HDIM, ln1_b + i*HDIM, yh_, yl_, nullptr);
        mma2<1><<<qkvgrid, 256, SMEM_MMA>>>(yh_, yl_, HDIM, wh_ + off, wl_ + off, HDIM,
            bqkv_ + i*QKVD, nullptr, qkvh_, qkvl_, nullptr, ROWS, QKVD, HDIM, QKVD);
        vtrans_kernel<<<vtgrid, wb32>>>();
        fa_kernel<<<fagrid, 256, SMEM_FA>>>();
        mma2<3><<<ggrid, 256, SMEM_MMA>>>(oh_, ol_, HDIM, wh_ + off + 3*HH, wl_ + off + 3*HH, HDIM,
            bo + i*HDIM, h_, nullptr, nullptr, h_, ROWS, HDIM, HDIM, HDIM);
        ln_kernel<false><<<lnGrid, 256>>>(h_, ln2_g + i*HDIM, ln2_b + i*HDIM, yh_, yl_, nullptr);
        mma2<2><<<fgrid, 256, SMEM_MMA>>>(yh_, yl_, HDIM, wh_ + off + 4*HH, wl_ + off + 4*HH, HDIM,
            b1 + i*FFND, nullptr, fh_, fl_, nullptr, ROWS, FFND, HDIM, FFND);
        mma2<3><<<ggrid, 256, SMEM_MMA>>>(fh_, fl_, FFND, wh_ + off + 4*HH + HF, wl_ + off + 4*HH + HF, FFND,
            b2 + i*HDIM, h_, nullptr, nullptr, h_, ROWS, HDIM, FFND, HDIM);
    }

    ln_kernel<true><<<lnGrid, 256>>>(h_, fln_g, fln_b, yh_, yl_, y_);
    readout_kernel<<<BATCH, 256>>>(out_W, out_b, (float*)d_out);
}